// round 1
// baseline (speedup 1.0000x reference)
#include <cuda_runtime.h>
#include <math.h>

#define Nn 100000
#define Ee 800000
#define NEGO 512
#define EEGO 4096
#define RR 5
#define HH 128
#define LOG2C 0.6931471805599453

// ---------------- scratch (device globals; no allocation allowed) ----------------
__device__ float g_hW[(size_t)RR * Nn * HH];   // 256 MB
__device__ float g_agg[(size_t)Nn * HH];       // 51 MB
__device__ float g_h1[(size_t)Nn * HH];        // 51 MB
__device__ float g_pos[(size_t)Nn * HH];       // 51 MB
__device__ float g_stats[256];
__device__ float g_fcx[NEGO * HH];
__device__ float g_sm[NEGO * HH];
__device__ float g_aM[NEGO * HH];
__device__ float g_cX[NEGO * HH];
__device__ float g_rP[NEGO * HH];
__device__ float g_rN[NEGO * HH];
__device__ int   g_pmax[NEGO];
__device__ int   g_ridxP[NEGO];
__device__ int   g_ridxN[NEGO];
__device__ double g_E[2];

// ---------------- zero/init ----------------
__global__ void zinit_k(float* stats, double* E) {
    int t = threadIdx.x;
    if (t < 256) stats[t] = 0.f;
    if (E != nullptr && t < 2) E[t] = 0.0;
}

// ---------------- generic GEMM: C[M,128] = A[rowidx?,128] @ B[128,128] (+bias) ----------------
// grid.y strides B by Bstride and C by Cstride (for the R-relation einsum).
__global__ void __launch_bounds__(256) gemm128_k(
    const float* __restrict__ A, const int* __restrict__ rowidx,
    const float* __restrict__ B, int Bstride,
    const float* __restrict__ bias,
    float* __restrict__ C, long long Cstride, int M)
{
    __shared__ float As[32][132];
    __shared__ float Bs[32][132];
    B += (long long)blockIdx.y * Bstride;
    C += (long long)blockIdx.y * Cstride;
    const int row0 = blockIdx.x * 128;
    const int tid = threadIdx.x;
    const int tx = tid & 15, ty = tid >> 4;
    float acc[8][8];
#pragma unroll
    for (int i = 0; i < 8; i++)
#pragma unroll
        for (int j = 0; j < 8; j++) acc[i][j] = 0.f;

    for (int kk = 0; kk < 128; kk += 32) {
#pragma unroll
        for (int i = 0; i < 4; i++) {
            int idx = tid + i * 256;           // 0..1023
            int r = idx >> 3;                  // row in tile
            int c4 = idx & 7;                  // float4 col
            int grow = row0 + r;
            float4 v = make_float4(0.f, 0.f, 0.f, 0.f);
            if (grow < M) {
                int ar = rowidx ? rowidx[grow] : grow;
                v = *(const float4*)(A + (long long)ar * 128 + kk + c4 * 4);
            }
            As[c4 * 4 + 0][r] = v.x;
            As[c4 * 4 + 1][r] = v.y;
            As[c4 * 4 + 2][r] = v.z;
            As[c4 * 4 + 3][r] = v.w;
        }
#pragma unroll
        for (int i = 0; i < 4; i++) {
            int idx = tid + i * 256;
            int r = idx >> 5;                  // 0..31
            int c4 = idx & 31;
            float4 v = *(const float4*)(B + (long long)(kk + r) * 128 + c4 * 4);
            *(float4*)&Bs[r][c4 * 4] = v;
        }
        __syncthreads();
#pragma unroll
        for (int k = 0; k < 32; k++) {
            float a[8], b[8];
#pragma unroll
            for (int i = 0; i < 8; i++) a[i] = As[k][ty * 8 + i];
#pragma unroll
            for (int j = 0; j < 8; j++) b[j] = Bs[k][tx * 8 + j];
#pragma unroll
            for (int i = 0; i < 8; i++)
#pragma unroll
                for (int j = 0; j < 8; j++) acc[i][j] += a[i] * b[j];
        }
        __syncthreads();
    }
#pragma unroll
    for (int i = 0; i < 8; i++) {
        int grow = row0 + ty * 8 + i;
        if (grow >= M) continue;
#pragma unroll
        for (int j = 0; j < 8; j++) {
            int col = tx * 8 + j;
            float v = acc[i][j];
            if (bias) v += bias[col];
            C[(long long)grow * 128 + col] = v;
        }
    }
}

// ---------------- edge scatter: agg[dst] += hW[etype][src] ----------------
__global__ void __launch_bounds__(256) scatter_k(
    const float* __restrict__ hW, const int* __restrict__ src,
    const int* __restrict__ dst, const int* __restrict__ et,
    float* __restrict__ agg)
{
    int gw = (int)((blockIdx.x * blockDim.x + threadIdx.x) >> 5);
    int lane = threadIdx.x & 31;
    if (gw >= Ee) return;
    int s = src[gw], d = dst[gw], r = et[gw];
    float4 v = *((const float4*)(hW + ((long long)r * Nn + s) * 128) + lane);
    float* q = agg + (long long)d * 128 + lane * 4;
    asm volatile("red.global.add.v4.f32 [%0], {%1,%2,%3,%4};"
                 :: "l"(q), "f"(v.x), "f"(v.y), "f"(v.z), "f"(v.w) : "memory");
}

// ---------------- BN stats over leaky_relu(X): per-col sum & sumsq ----------------
__global__ void __launch_bounds__(256) bnstats_k(const float* __restrict__ X, float* __restrict__ stats) {
    int col = threadIdx.x & 127;
    int half = threadIdx.x >> 7;
    float s = 0.f, s2 = 0.f;
    for (long long r = (long long)blockIdx.x * 2 + half; r < Nn; r += (long long)gridDim.x * 2) {
        float v = X[r * 128 + col];
        v = v >= 0.f ? v : 0.01f * v;
        s += v; s2 += v * v;
    }
    __shared__ float sh[256], sh2[256];
    sh[threadIdx.x] = s; sh2[threadIdx.x] = s2;
    __syncthreads();
    if (half == 0) {
        atomicAdd(&stats[col], s + sh[col + 128]);
        atomicAdd(&stats[128 + col], s2 + sh2[col + 128]);
    }
}

// ---------------- BN apply + relu: Y = relu((lrelu(X)-m)*rsqrt(v+eps)) ----------------
__global__ void __launch_bounds__(256) bnapply_k(const float4* __restrict__ X,
                                                 const float* __restrict__ stats,
                                                 float4* __restrict__ Y)
{
    long long i = (long long)blockIdx.x * blockDim.x + threadIdx.x;
    if (i >= (long long)Nn * 32) return;
    int c4 = (int)(i & 31);
    float4 x = X[i];
    float o[4]; float in[4] = {x.x, x.y, x.z, x.w};
#pragma unroll
    for (int j = 0; j < 4; j++) {
        int col = c4 * 4 + j;
        float mean = stats[col] * (1.0f / Nn);
        float var = stats[128 + col] * (1.0f / Nn) - mean * mean;
        float v = in[j];
        v = v >= 0.f ? v : 0.01f * v;
        float y = (v - mean) * rsqrtf(var + 1e-5f);
        o[j] = y > 0.f ? y : 0.f;
    }
    Y[i] = make_float4(o[0], o[1], o[2], o[3]);
}

// ---------------- disc structure: adjacency, p_max, rep chain, root indices ----------------
__global__ void __launch_bounds__(512) discprep_k(
    const int* __restrict__ es, const int* __restrict__ ed,
    const int* __restrict__ ego, const int* __restrict__ perm,
    int* __restrict__ pmax, int* __restrict__ ridxP, int* __restrict__ ridxN)
{
    __shared__ unsigned adj[NEGO][16];
    __shared__ int spm[NEGO];
    __shared__ int rep[NEGO];
    int t = threadIdx.x;
#pragma unroll
    for (int w = 0; w < 16; w++) adj[t][w] = 0u;
    __syncthreads();
    for (int e = t; e < EEGO; e += 512) {
        int s = es[e], d = ed[e];
        if (s < d) atomicOr(&adj[d][s >> 5], 1u << (s & 31));
    }
    __syncthreads();
    int p = -1;
    int wj = t >> 5, bj = t & 31;
    unsigned m = bj ? (adj[t][wj] & ((1u << bj) - 1u)) : 0u;
    if (m) p = wj * 32 + 31 - __clz(m);
    for (int w = wj - 1; w >= 0 && p < 0; w--) {
        unsigned mm = adj[t][w];
        if (mm) p = w * 32 + 31 - __clz(mm);
    }
    spm[t] = p;
    pmax[t] = p;
    __syncthreads();
    if (t == 0) {
        for (int i = 0; i < NEGO; i++) {
            int pi = spm[i];
            rep[i] = (pi < 0) ? i : rep[pi];
        }
    }
    __syncthreads();
    int rid = ego[rep[t]];
    ridxP[t] = rid;
    ridxN[t] = perm[rid];
}

// ---------------- sequential snap_m recurrence (shared by pos & neg disc) ----------------
__global__ void __launch_bounds__(512) scan_k(
    const float* __restrict__ Wfc, const float* __restrict__ bfc,
    const float* __restrict__ fcx, const int* __restrict__ pmax,
    float* __restrict__ sm)
{
    __shared__ float sp[128];
    __shared__ float red[512];
    __shared__ int pm[NEGO];
    int t = threadIdx.x;
    pm[t] = pmax[t];
    int col = t & 127;
    int q = t >> 7;
    __syncthreads();
    for (int i = 0; i < NEGO; i++) {
        int p = pm[i];                      // uniform across block
        if (p >= 0 && p != 1) {
            if (t < 128) sp[t] = sm[p * 128 + t];
            __syncthreads();
            float partial = 0.f;
            const float* wc = Wfc + col;
#pragma unroll
            for (int k = 0; k < 32; k++) partial += sp[q * 32 + k] * wc[(q * 32 + k) * 128];
            red[t] = partial;
        }
        __syncthreads();
        if (t < 128) {
            float v = 0.f;
            if (p >= 0) {
                float msg = (p == 1) ? fcx[128 + col]
                                     : (red[col] + red[col + 128] + red[col + 256] + red[col + 384] + bfc[col]);
                v = fcx[i * 128 + col] + msg;
                v = v > 0.f ? v : 0.f;
            }
            sm[i * 128 + col] = v;
        }
        __syncthreads();
    }
}

// ---------------- per-edge logits + JSD accumulation ----------------
__device__ __forceinline__ double softplus_d(double z) {
    return (z > 0.0) ? z + log1p(exp(-z)) : log1p(exp(z));
}

__global__ void __launch_bounds__(256) edgelogit_k(
    const int* __restrict__ es, const int* __restrict__ ed,
    const float* __restrict__ rP, const float* __restrict__ rN,
    const float* __restrict__ aM, const float* __restrict__ cX,
    const float* __restrict__ blin, const float* __restrict__ Wus,
    const float* __restrict__ bus, double* __restrict__ Eacc)
{
    int gw = (int)((blockIdx.x * blockDim.x + threadIdx.x) >> 5);
    int lane = threadIdx.x & 31;
    if (gw >= EEGO) return;
    int s = es[gw], d = ed[gw];
    float lp = 0.f, ln = 0.f;
#pragma unroll
    for (int j = 0; j < 4; j++) {
        int c = lane * 4 + j;
        float base = aM[s * 128 + c] + cX[d * 128 + c] + blin[c];
        float w = Wus[c];
        float hp = base + rP[s * 128 + c]; hp = hp > 0.f ? hp : 0.f;
        float hn = base + rN[s * 128 + c]; hn = hn > 0.f ? hn : 0.f;
        lp += hp * w; ln += hn * w;
    }
#pragma unroll
    for (int o = 16; o; o >>= 1) {
        lp += __shfl_xor_sync(0xffffffffu, lp, o);
        ln += __shfl_xor_sync(0xffffffffu, ln, o);
    }
    if (lane == 0) {
        float bu = bus[0];
        double zp = (double)(lp + bu);
        double zn = (double)(ln + bu);
        atomicAdd(&Eacc[0], LOG2C - softplus_d(-zp));          // E_pos terms
        atomicAdd(&Eacc[1], softplus_d(-zn) + zn - LOG2C);     // E_neg terms
    }
}

__global__ void final_k(const double* __restrict__ E, float* __restrict__ out) {
    out[0] = (float)((E[1] - E[0]) * (1.0 / (double)EEGO));
}

// ---------------- host ----------------
extern "C" void kernel_launch(void* const* d_in, const int* in_sizes, int n_in,
                              void* d_out, int out_size) {
    const float* features = (const float*)d_in[0];
    const float* W1     = (const float*)d_in[1];
    const float* Wloop1 = (const float*)d_in[2];
    const float* b1     = (const float*)d_in[3];
    const float* W2     = (const float*)d_in[4];
    const float* Wloop2 = (const float*)d_in[5];
    const float* b2     = (const float*)d_in[6];
    const float* Wfc    = (const float*)d_in[7];
    const float* bfc    = (const float*)d_in[8];
    const float* Wlin   = (const float*)d_in[9];
    const float* blin   = (const float*)d_in[10];
    const float* Wus    = (const float*)d_in[11];
    const float* bus    = (const float*)d_in[12];
    const int* src      = (const int*)d_in[13];
    const int* dst      = (const int*)d_in[14];
    const int* etype    = (const int*)d_in[15];
    const int* perm     = (const int*)d_in[16];
    const int* ego_ids  = (const int*)d_in[17];
    const int* ego_src  = (const int*)d_in[18];
    const int* ego_dst  = (const int*)d_in[19];

    float *hW, *agg, *h1, *pos, *stats, *fcx, *sm, *aM, *cX, *rP, *rN;
    int *pmax, *ridxP, *ridxN;
    double* Eacc;
    cudaGetSymbolAddress((void**)&hW, g_hW);
    cudaGetSymbolAddress((void**)&agg, g_agg);
    cudaGetSymbolAddress((void**)&h1, g_h1);
    cudaGetSymbolAddress((void**)&pos, g_pos);
    cudaGetSymbolAddress((void**)&stats, g_stats);
    cudaGetSymbolAddress((void**)&fcx, g_fcx);
    cudaGetSymbolAddress((void**)&sm, g_sm);
    cudaGetSymbolAddress((void**)&aM, g_aM);
    cudaGetSymbolAddress((void**)&cX, g_cX);
    cudaGetSymbolAddress((void**)&rP, g_rP);
    cudaGetSymbolAddress((void**)&rN, g_rN);
    cudaGetSymbolAddress((void**)&pmax, g_pmax);
    cudaGetSymbolAddress((void**)&ridxP, g_ridxP);
    cudaGetSymbolAddress((void**)&ridxN, g_ridxN);
    cudaGetSymbolAddress((void**)&Eacc, g_E);

    const int mt = (Nn + 127) / 128;           // 782 row tiles
    const int scat_blocks = (Ee * 32) / 256;   // 100000
    const int bna_blocks = (Nn * 32 + 255) / 256;

    zinit_k<<<1, 256>>>(stats, Eacc);

    // ---- encoder layer 1 ----
    gemm128_k<<<dim3(mt, RR), 256>>>(features, nullptr, W1, 128 * 128, nullptr, hW, (long long)Nn * 128, Nn);
    gemm128_k<<<dim3(mt, 1), 256>>>(features, nullptr, Wloop1, 0, b1, agg, 0, Nn);
    scatter_k<<<scat_blocks, 256>>>(hW, src, dst, etype, agg);
    bnstats_k<<<512, 256>>>(agg, stats);
    bnapply_k<<<bna_blocks, 256>>>((const float4*)agg, stats, (float4*)h1);

    // ---- encoder layer 2 ----
    zinit_k<<<1, 256>>>(stats, nullptr);
    gemm128_k<<<dim3(mt, RR), 256>>>(h1, nullptr, W2, 128 * 128, nullptr, hW, (long long)Nn * 128, Nn);
    gemm128_k<<<dim3(mt, 1), 256>>>(h1, nullptr, Wloop2, 0, b2, agg, 0, Nn);
    scatter_k<<<scat_blocks, 256>>>(hW, src, dst, etype, agg);
    bnstats_k<<<512, 256>>>(agg, stats);
    bnapply_k<<<bna_blocks, 256>>>((const float4*)agg, stats, (float4*)pos);

    // ---- discriminator (structure shared by pos & neg) ----
    discprep_k<<<1, 512>>>(ego_src, ego_dst, ego_ids, perm, pmax, ridxP, ridxN);
    gemm128_k<<<dim3(4, 1), 256>>>(features, ego_ids, Wfc, 0, bfc, fcx, 0, NEGO);
    scan_k<<<1, 512>>>(Wfc, bfc, fcx, pmax, sm);
    gemm128_k<<<dim3(4, 1), 256>>>(sm, nullptr, Wlin + 128 * 128, 0, nullptr, aM, 0, NEGO);
    gemm128_k<<<dim3(4, 1), 256>>>(features, ego_ids, Wlin + 256 * 128, 0, nullptr, cX, 0, NEGO);
    gemm128_k<<<dim3(4, 1), 256>>>(pos, ridxP, Wlin, 0, nullptr, rP, 0, NEGO);
    gemm128_k<<<dim3(4, 1), 256>>>(pos, ridxN, Wlin, 0, nullptr, rN, 0, NEGO);
    edgelogit_k<<<512, 256>>>(ego_src, ego_dst, rP, rN, aM, cX, blin, Wus, bus, Eacc);
    final_k<<<1, 1>>>(Eacc, (float*)d_out);
}

// round 4
// speedup vs baseline: 1.5028x; 1.5028x over previous
#include <cuda_runtime.h>
#include <cuda_bf16.h>
#include <stdint.h>
#include <math.h>

#define Nn 100000
#define Ee 800000
#define NEGO 512
#define EEGO 4096
#define RR 5
#define HH 128
#define LOG2C 0.6931471805599453

// ---------------- scratch (device globals; no allocation allowed) ----------------
__device__ float g_hW[(size_t)RR * Nn * HH];   // 256 MB
__device__ float g_agg[(size_t)Nn * HH];       // 51 MB
__device__ float g_h1[(size_t)Nn * HH];        // 51 MB
__device__ float g_pos[(size_t)Nn * HH];       // 51 MB
__device__ float g_stats[256];
__device__ float g_fcx[NEGO * HH];
__device__ float g_sm[NEGO * HH];
__device__ float g_aM[NEGO * HH];
__device__ float g_cX[NEGO * HH];
__device__ float g_rP[NEGO * HH];
__device__ float g_rN[NEGO * HH];
__device__ int   g_pmax[NEGO];
__device__ int   g_ridxP[NEGO];
__device__ int   g_ridxN[NEGO];
__device__ double g_E[2];
// transposed bf16 weight images [N=128][Kpad=136] per mat:
// layout: [layer(2)][half(2: hi,lo)][mat(6)][17408]
#define LPAD 136
#define MATSZ (128 * LPAD)   // 17408 halves
__device__ __align__(256) unsigned short g_Bt[2 * 2 * 6 * MATSZ];

// ---------------- PTX helpers (baseline sm_100-legal: ldmatrix + mma.sync) ----------------
__device__ __forceinline__ uint32_t smem_u32(const void* p) {
    uint32_t a;
    asm("{ .reg .u64 t; cvta.to.shared.u64 t, %1; cvt.u32.u64 %0, t; }" : "=r"(a) : "l"(p));
    return a;
}
__device__ __forceinline__ void ldm_x4(uint32_t& r0, uint32_t& r1, uint32_t& r2, uint32_t& r3, uint32_t addr) {
    asm volatile("ldmatrix.sync.aligned.m8n8.x4.shared.b16 {%0,%1,%2,%3}, [%4];"
                 : "=r"(r0), "=r"(r1), "=r"(r2), "=r"(r3) : "r"(addr));
}
__device__ __forceinline__ void ldm_x2(uint32_t& r0, uint32_t& r1, uint32_t addr) {
    asm volatile("ldmatrix.sync.aligned.m8n8.x2.shared.b16 {%0,%1}, [%2];"
                 : "=r"(r0), "=r"(r1) : "r"(addr));
}
__device__ __forceinline__ void mma_bf16(float* d, const uint32_t* a, const uint32_t* b) {
    asm volatile("mma.sync.aligned.m16n8k16.row.col.f32.bf16.bf16.f32 "
                 "{%0,%1,%2,%3}, {%4,%5,%6,%7}, {%8,%9}, {%0,%1,%2,%3};"
                 : "+f"(d[0]), "+f"(d[1]), "+f"(d[2]), "+f"(d[3])
                 : "r"(a[0]), "r"(a[1]), "r"(a[2]), "r"(a[3]), "r"(b[0]), "r"(b[1]));
}

// ---------------- weight prep: transpose + hi/lo split into padded [N][Kpad] ----------------
__global__ void wprep_k(const float* __restrict__ W, const float* __restrict__ Wloop, int layer)
{
    int r = blockIdx.x;
    unsigned short* oh = g_Bt + layer * (2 * 6 * MATSZ) + r * MATSZ;
    unsigned short* ol = oh + 6 * MATSZ;
    const float* src = (r < 5) ? (W + r * 16384) : Wloop;
    for (int idx = threadIdx.x; idx < 16384; idx += blockDim.x) {
        int n = idx >> 7, k = idx & 127;
        float x = src[k * 128 + n];
        __nv_bfloat16 h = __float2bfloat16(x);
        __nv_bfloat16 l = __float2bfloat16(x - __bfloat162float(h));
        oh[n * LPAD + k] = *(unsigned short*)&h;
        ol[n * LPAD + k] = *(unsigned short*)&l;
    }
}

// ---------------- fused relation GEMM (tensor cores via mma.sync bf16-split) ----------------
// SMEM: A_hi[128][136], A_lo, B_hi[128][136], B_lo (bf16 each, 34816 B per buffer)
#define SA_HI 0
#define SA_LO 34816
#define SB_HI 69632
#define SB_LO 104448
#define SMEM_DYN 139264

__global__ void __launch_bounds__(128, 1) rgemm_k(const float* __restrict__ Aext,
                                                  const float* __restrict__ bias, int layer)
{
    extern __shared__ char dsm[];
    const float* A = (layer == 0) ? Aext : g_h1;
    uint32_t sbase = smem_u32(dsm);
    int tid = threadIdx.x;
    int w = tid >> 5, lane = tid & 31;
    int row0 = blockIdx.x * 128;
    const unsigned short* BtHi = g_Bt + layer * (2 * 6 * MATSZ);
    const unsigned short* BtLo = BtHi + 6 * MATSZ;

    // ---- convert A tile (128 rows x 128 cols) to hi/lo bf16 padded SMEM (coalesced) ----
    {
        uint32_t* ah = (uint32_t*)(dsm + SA_HI);
        uint32_t* al = (uint32_t*)(dsm + SA_LO);
        for (int i = tid; i < 128 * 64; i += 128) {
            int n = i >> 6, kp = i & 63;
            int grow = row0 + n;
            uint32_t ph = 0u, pl = 0u;
            if (grow < Nn) {
                float2 x = *((const float2*)(A + (long long)grow * 128) + kp);
                __nv_bfloat16 h0 = __float2bfloat16(x.x);
                __nv_bfloat16 h1 = __float2bfloat16(x.y);
                __nv_bfloat16 l0 = __float2bfloat16(x.x - __bfloat162float(h0));
                __nv_bfloat16 l1 = __float2bfloat16(x.y - __bfloat162float(h1));
                ph = ((uint32_t)(*(unsigned short*)&h1) << 16) | (*(unsigned short*)&h0);
                pl = ((uint32_t)(*(unsigned short*)&l1) << 16) | (*(unsigned short*)&l0);
            }
            ah[n * (LPAD / 2) + kp] = ph;   // LPAD even: uint32 index = n*68+kp
            al[n * (LPAD / 2) + kp] = pl;
        }
    }

    // warp tiling: 2x2 warps, each 64(m) x 64(n)
    int wm0 = (w >> 1) * 64;
    int wn0 = (w & 1) * 64;
    // ldmatrix lane address components
    int a_row = (lane & 15);            // + mi*16 + wm0
    int a_koff = (lane >> 4) << 3;      // 0 or 8
    int b_n = (lane & 7);               // + nj*8 + wn0
    int b_koff = ((lane >> 3) & 1) << 3;

    for (int r = 0; r < 6; r++) {
        __syncthreads();   // prior-iter SMEM B reads done before overwrite
        // copy B mat (hi+lo) L2 -> SMEM, raw (pre-padded layout)
        {
            const float4* shp = (const float4*)(BtHi + r * MATSZ);
            const float4* slp = (const float4*)(BtLo + r * MATSZ);
            float4* dh = (float4*)(dsm + SB_HI);
            float4* dl = (float4*)(dsm + SB_LO);
            for (int i = tid; i < MATSZ / 8; i += 128) { dh[i] = shp[i]; dl[i] = slp[i]; }
        }
        __syncthreads();

        float acc[4][8][4];
#pragma unroll
        for (int mi = 0; mi < 4; mi++)
#pragma unroll
            for (int nj = 0; nj < 8; nj++)
#pragma unroll
                for (int q = 0; q < 4; q++) acc[mi][nj][q] = 0.f;

#pragma unroll
        for (int s = 0; s < 3; s++) {
            uint32_t abase = sbase + ((s == 2) ? SA_LO : SA_HI);
            uint32_t bbase = sbase + ((s == 1) ? SB_LO : SB_HI);
#pragma unroll
            for (int kk = 0; kk < 8; kk++) {
                int k0 = kk * 16;
                uint32_t bfrag[8][2];
#pragma unroll
                for (int nj = 0; nj < 8; nj++) {
                    uint32_t addr = bbase + (uint32_t)(((wn0 + nj * 8 + b_n) * LPAD + k0 + b_koff) * 2);
                    ldm_x2(bfrag[nj][0], bfrag[nj][1], addr);
                }
                uint32_t afrag[4][4];
#pragma unroll
                for (int mi = 0; mi < 4; mi++) {
                    uint32_t addr = abase + (uint32_t)(((wm0 + mi * 16 + a_row) * LPAD + k0 + a_koff) * 2);
                    ldm_x4(afrag[mi][0], afrag[mi][1], afrag[mi][2], afrag[mi][3], addr);
                }
#pragma unroll
                for (int mi = 0; mi < 4; mi++)
#pragma unroll
                    for (int nj = 0; nj < 8; nj++)
                        mma_bf16(acc[mi][nj], afrag[mi], bfrag[nj]);
            }
        }

        // write out: thread t covers rows (t/4, t/4+8) of each m16, cols 2*(t%4)+{0,1} of each n8
        int qr = lane >> 2, qc = lane & 3;
        float* outbase = (r < 5) ? (g_hW + (long long)r * Nn * 128) : g_agg;
#pragma unroll
        for (int mi = 0; mi < 4; mi++) {
            int grow0 = row0 + wm0 + mi * 16 + qr;
#pragma unroll
            for (int half = 0; half < 2; half++) {
                int grow = grow0 + half * 8;
                if (grow < Nn) {
                    float* op = outbase + (long long)grow * 128;
#pragma unroll
                    for (int nj = 0; nj < 8; nj++) {
                        int col = wn0 + nj * 8 + qc * 2;
                        float2 v;
                        v.x = acc[mi][nj][half * 2 + 0];
                        v.y = acc[mi][nj][half * 2 + 1];
                        if (r == 5) { v.x += bias[col]; v.y += bias[col + 1]; }
                        *(float2*)(op + col) = v;
                    }
                }
            }
        }
    }
}

// ---------------- zero/init ----------------
__global__ void zinit_k(int both) {
    int t = threadIdx.x;
    if (t < 256) g_stats[t] = 0.f;
    if (both && t < 2) g_E[t] = 0.0;
}

// ---------------- small FFMA GEMM for disc (M=512) ----------------
// asel: 0=Aext  1=g_pos  2=g_sm ; rsel: 0=none 1=ext(ridx) 2=g_ridxP 3=g_ridxN
// csel: 0=g_fcx 1=g_aM 2=g_cX 3=g_rP 4=g_rN
__global__ void __launch_bounds__(256) gemm128_k(
    const float* __restrict__ Aext, int asel,
    const int* __restrict__ ridxExt, int rsel,
    const float* __restrict__ B, const float* __restrict__ bias, int csel)
{
    const float* A = (asel == 0) ? Aext : (asel == 1 ? g_pos : g_sm);
    const int* rowidx = (rsel == 0) ? (const int*)0
                      : (rsel == 1) ? ridxExt
                      : (rsel == 2) ? g_ridxP : g_ridxN;
    float* C = (csel == 0) ? g_fcx : (csel == 1) ? g_aM : (csel == 2) ? g_cX
             : (csel == 3) ? g_rP : g_rN;
    __shared__ float As[32][132];
    __shared__ float Bs[32][132];
    const int row0 = blockIdx.x * 128;
    const int tid = threadIdx.x;
    const int tx = tid & 15, ty = tid >> 4;
    float acc[8][8];
#pragma unroll
    for (int i = 0; i < 8; i++)
#pragma unroll
        for (int j = 0; j < 8; j++) acc[i][j] = 0.f;

    for (int kk = 0; kk < 128; kk += 32) {
#pragma unroll
        for (int i = 0; i < 4; i++) {
            int idx = tid + i * 256;
            int rw = idx >> 3;
            int c4 = idx & 7;
            int grow = row0 + rw;
            float4 v = make_float4(0.f, 0.f, 0.f, 0.f);
            if (grow < NEGO) {
                int ar = rowidx ? rowidx[grow] : grow;
                v = *(const float4*)(A + (long long)ar * 128 + kk + c4 * 4);
            }
            As[c4 * 4 + 0][rw] = v.x;
            As[c4 * 4 + 1][rw] = v.y;
            As[c4 * 4 + 2][rw] = v.z;
            As[c4 * 4 + 3][rw] = v.w;
        }
#pragma unroll
        for (int i = 0; i < 4; i++) {
            int idx = tid + i * 256;
            int rw = idx >> 5;
            int c4 = idx & 31;
            float4 v = *(const float4*)(B + (long long)(kk + rw) * 128 + c4 * 4);
            *(float4*)&Bs[rw][c4 * 4] = v;
        }
        __syncthreads();
#pragma unroll
        for (int k = 0; k < 32; k++) {
            float a[8], b[8];
#pragma unroll
            for (int i = 0; i < 8; i++) a[i] = As[k][ty * 8 + i];
#pragma unroll
            for (int j = 0; j < 8; j++) b[j] = Bs[k][tx * 8 + j];
#pragma unroll
            for (int i = 0; i < 8; i++)
#pragma unroll
                for (int j = 0; j < 8; j++) acc[i][j] += a[i] * b[j];
        }
        __syncthreads();
    }
#pragma unroll
    for (int i = 0; i < 8; i++) {
        int grow = row0 + ty * 8 + i;
        if (grow >= NEGO) continue;
#pragma unroll
        for (int j = 0; j < 8; j++) {
            int col = tx * 8 + j;
            float v = acc[i][j];
            if (bias) v += bias[col];
            C[(long long)grow * 128 + col] = v;
        }
    }
}

// ---------------- edge scatter: g_agg[dst] += g_hW[etype][src] ----------------
__global__ void __launch_bounds__(256) scatter_k(
    const int* __restrict__ src, const int* __restrict__ dst, const int* __restrict__ et)
{
    int gw = (int)((blockIdx.x * blockDim.x + threadIdx.x) >> 5);
    int lane = threadIdx.x & 31;
    if (gw >= Ee) return;
    int s = src[gw], d = dst[gw], r = et[gw];
    float4 v = *((const float4*)(g_hW + ((long long)r * Nn + s) * 128) + lane);
    float* q = g_agg + (long long)d * 128 + lane * 4;
    asm volatile("red.global.add.v4.f32 [%0], {%1,%2,%3,%4};"
                 :: "l"(q), "f"(v.x), "f"(v.y), "f"(v.z), "f"(v.w) : "memory");
}

// ---------------- BN stats over leaky_relu(g_agg): per-col sum & sumsq ----------------
__global__ void __launch_bounds__(256) bnstats_k()
{
    int col = threadIdx.x & 127;
    int half = threadIdx.x >> 7;
    float s = 0.f, s2 = 0.f;
    for (long long r = (long long)blockIdx.x * 2 + half; r < Nn; r += (long long)gridDim.x * 2) {
        float v = g_agg[r * 128 + col];
        v = v >= 0.f ? v : 0.01f * v;
        s += v; s2 += v * v;
    }
    __shared__ float sh[256], sh2[256];
    sh[threadIdx.x] = s; sh2[threadIdx.x] = s2;
    __syncthreads();
    if (half == 0) {
        atomicAdd(&g_stats[col], s + sh[col + 128]);
        atomicAdd(&g_stats[128 + col], s2 + sh2[col + 128]);
    }
}

// ---------------- BN apply + relu ----------------
__global__ void __launch_bounds__(256) bnapply_k(int layer)
{
    long long i = (long long)blockIdx.x * blockDim.x + threadIdx.x;
    if (i >= (long long)Nn * 32) return;
    float4* Y = (float4*)(layer == 0 ? g_h1 : g_pos);
    int c4 = (int)(i & 31);
    float4 x = ((const float4*)g_agg)[i];
    float o[4]; float in[4] = {x.x, x.y, x.z, x.w};
#pragma unroll
    for (int j = 0; j < 4; j++) {
        int col = c4 * 4 + j;
        float mean = g_stats[col] * (1.0f / Nn);
        float var = g_stats[128 + col] * (1.0f / Nn) - mean * mean;
        float v = in[j];
        v = v >= 0.f ? v : 0.01f * v;
        float y = (v - mean) * rsqrtf(var + 1e-5f);
        o[j] = y > 0.f ? y : 0.f;
    }
    Y[i] = make_float4(o[0], o[1], o[2], o[3]);
}

// ---------------- disc structure prep ----------------
__global__ void __launch_bounds__(512) discprep_k(
    const int* __restrict__ es, const int* __restrict__ ed,
    const int* __restrict__ ego, const int* __restrict__ perm)
{
    __shared__ unsigned adj[NEGO][16];
    __shared__ int spm[NEGO];
    __shared__ int rep[NEGO];
    int t = threadIdx.x;
#pragma unroll
    for (int w = 0; w < 16; w++) adj[t][w] = 0u;
    __syncthreads();
    for (int e = t; e < EEGO; e += 512) {
        int s = es[e], d = ed[e];
        if (s < d) atomicOr(&adj[d][s >> 5], 1u << (s & 31));
    }
    __syncthreads();
    int p = -1;
    int wj = t >> 5, bj = t & 31;
    unsigned m = bj ? (adj[t][wj] & ((1u << bj) - 1u)) : 0u;
    if (m) p = wj * 32 + 31 - __clz(m);
    for (int w = wj - 1; w >= 0 && p < 0; w--) {
        unsigned mm = adj[t][w];
        if (mm) p = w * 32 + 31 - __clz(mm);
    }
    spm[t] = p;
    g_pmax[t] = p;
    __syncthreads();
    if (t == 0) {
        for (int i = 0; i < NEGO; i++) {
            int pi = spm[i];
            rep[i] = (pi < 0) ? i : rep[pi];
        }
    }
    __syncthreads();
    int rid = ego[rep[t]];
    g_ridxP[t] = rid;
    g_ridxN[t] = perm[rid];
}

// ---------------- sequential snap_m recurrence ----------------
__global__ void __launch_bounds__(512) scan_k(
    const float* __restrict__ Wfc, const float* __restrict__ bfc)
{
    __shared__ float sp[128];
    __shared__ float red[512];
    __shared__ int pm[NEGO];
    int t = threadIdx.x;
    pm[t] = g_pmax[t];
    int col = t & 127;
    int q = t >> 7;
    __syncthreads();
    for (int i = 0; i < NEGO; i++) {
        int p = pm[i];
        if (p >= 0 && p != 1) {
            if (t < 128) sp[t] = g_sm[p * 128 + t];
            __syncthreads();
            float partial = 0.f;
            const float* wc = Wfc + col;
#pragma unroll
            for (int k = 0; k < 32; k++) partial += sp[q * 32 + k] * wc[(q * 32 + k) * 128];
            red[t] = partial;
        }
        __syncthreads();
        if (t < 128) {
            float v = 0.f;
            if (p >= 0) {
                float msg = (p == 1) ? g_fcx[128 + col]
                                     : (red[col] + red[col + 128] + red[col + 256] + red[col + 384] + bfc[col]);
                v = g_fcx[i * 128 + col] + msg;
                v = v > 0.f ? v : 0.f;
            }
            g_sm[i * 128 + col] = v;
        }
        __syncthreads();
    }
}

// ---------------- per-edge logits + JSD accumulation ----------------
__device__ __forceinline__ double softplus_d(double z) {
    return (z > 0.0) ? z + log1p(exp(-z)) : log1p(exp(z));
}

__global__ void __launch_bounds__(256) edgelogit_k(
    const int* __restrict__ es, const int* __restrict__ ed,
    const float* __restrict__ blin, const float* __restrict__ Wus,
    const float* __restrict__ bus)
{
    int gw = (int)((blockIdx.x * blockDim.x + threadIdx.x) >> 5);
    int lane = threadIdx.x & 31;
    if (gw >= EEGO) return;
    int s = es[gw], d = ed[gw];
    float lp = 0.f, ln = 0.f;
#pragma unroll
    for (int j = 0; j < 4; j++) {
        int c = lane * 4 + j;
        float base = g_aM[s * 128 + c] + g_cX[d * 128 + c] + blin[c];
        float w = Wus[c];
        float hp = base + g_rP[s * 128 + c]; hp = hp > 0.f ? hp : 0.f;
        float hn = base + g_rN[s * 128 + c]; hn = hn > 0.f ? hn : 0.f;
        lp += hp * w; ln += hn * w;
    }
#pragma unroll
    for (int o = 16; o; o >>= 1) {
        lp += __shfl_xor_sync(0xffffffffu, lp, o);
        ln += __shfl_xor_sync(0xffffffffu, ln, o);
    }
    if (lane == 0) {
        float bu = bus[0];
        double zp = (double)(lp + bu);
        double zn = (double)(ln + bu);
        atomicAdd(&g_E[0], LOG2C - softplus_d(-zp));
        atomicAdd(&g_E[1], softplus_d(-zn) + zn - LOG2C);
    }
}

__global__ void final_k(float* __restrict__ outp) {
    outp[0] = (float)((g_E[1] - g_E[0]) * (1.0 / (double)EEGO));
}

// ---------------- host ----------------
extern "C" void kernel_launch(void* const* d_in, const int* in_sizes, int n_in,
                              void* d_out, int out_size) {
    const float* features = (const float*)d_in[0];
    const float* W1     = (const float*)d_in[1];
    const float* Wloop1 = (const float*)d_in[2];
    const float* b1     = (const float*)d_in[3];
    const float* W2     = (const float*)d_in[4];
    const float* Wloop2 = (const float*)d_in[5];
    const float* b2     = (const float*)d_in[6];
    const float* Wfc    = (const float*)d_in[7];
    const float* bfc    = (const float*)d_in[8];
    const float* Wlin   = (const float*)d_in[9];
    const float* blin   = (const float*)d_in[10];
    const float* Wus    = (const float*)d_in[11];
    const float* bus    = (const float*)d_in[12];
    const int* src      = (const int*)d_in[13];
    const int* dst      = (const int*)d_in[14];
    const int* etype    = (const int*)d_in[15];
    const int* perm     = (const int*)d_in[16];
    const int* ego_ids  = (const int*)d_in[17];
    const int* ego_src  = (const int*)d_in[18];
    const int* ego_dst  = (const int*)d_in[19];

    cudaFuncSetAttribute(rgemm_k, cudaFuncAttributeMaxDynamicSharedMemorySize, SMEM_DYN);

    const int mt = (Nn + 127) / 128;           // 782 row tiles
    const int scat_blocks = (Ee * 32) / 256;   // 100000
    const int bna_blocks = (Nn * 32 + 255) / 256;

    zinit_k<<<1, 256>>>(1);
    wprep_k<<<6, 256>>>(W1, Wloop1, 0);
    wprep_k<<<6, 256>>>(W2, Wloop2, 1);

    // ---- encoder layer 1 ----
    rgemm_k<<<mt, 128, SMEM_DYN>>>(features, b1, 0);
    scatter_k<<<scat_blocks, 256>>>(src, dst, etype);
    bnstats_k<<<512, 256>>>();
    bnapply_k<<<bna_blocks, 256>>>(0);

    // ---- encoder layer 2 ----
    zinit_k<<<1, 256>>>(0);
    rgemm_k<<<mt, 128, SMEM_DYN>>>(features, b2, 1);
    scatter_k<<<scat_blocks, 256>>>(src, dst, etype);
    bnstats_k<<<512, 256>>>();
    bnapply_k<<<bna_blocks, 256>>>(1);

    // ---- discriminator ----
    discprep_k<<<1, 512>>>(ego_src, ego_dst, ego_ids, perm);
    gemm128_k<<<4, 256>>>(features, 0, ego_ids, 1, Wfc, bfc, 0);            // fcx
    scan_k<<<1, 512>>>(Wfc, bfc);
    gemm128_k<<<4, 256>>>((const float*)0, 2, (const int*)0, 0, Wlin + 128 * 128, (const float*)0, 1); // aM from sm
    gemm128_k<<<4, 256>>>(features, 0, ego_ids, 1, Wlin + 256 * 128, (const float*)0, 2);              // cX
    gemm128_k<<<4, 256>>>((const float*)0, 1, (const int*)0, 2, Wlin, (const float*)0, 3);             // rP
    gemm128_k<<<4, 256>>>((const float*)0, 1, (const int*)0, 3, Wlin, (const float*)0, 4);             // rN
    edgelogit_k<<<512, 256>>>(ego_src, ego_dst, blin, Wus, bus);
    final_k<<<1, 1>>>((float*)d_out);
}

// round 7
// speedup vs baseline: 1.8062x; 1.2019x over previous
#include <cuda_runtime.h>
#include <cuda_bf16.h>
#include <stdint.h>
#include <math.h>

#define Nn 100000
#define Ee 800000
#define NEGO 512
#define EEGO 4096
#define RR 5
#define HH 128
#define LOG2C 0.6931471805599453

// ---------------- scratch (device globals; no allocation allowed) ----------------
__device__ float g_hW[(size_t)RR * Nn * HH];   // 256 MB
__device__ float g_agg[(size_t)Nn * HH];       // 51 MB
__device__ float g_h1[(size_t)Nn * HH];        // 51 MB
__device__ float g_pos[(size_t)Nn * HH];       // 51 MB
__device__ float g_stats[256];
__device__ float g_fcx[NEGO * HH];
__device__ float g_sm[NEGO * HH];
__device__ float g_aM[NEGO * HH];
__device__ float g_cX[NEGO * HH];
__device__ float g_rP[NEGO * HH];
__device__ float g_rN[NEGO * HH];
__device__ int   g_pmax[NEGO];
__device__ int   g_ridxP[NEGO];
__device__ int   g_ridxN[NEGO];
__device__ double g_E[2];
// transposed bf16 weight images [N=128][Kpad=136] per mat:
// layout: [layer(2)][half(2: hi,lo)][mat(6)][17408]
#define LPAD 136
#define MATSZ (128 * LPAD)   // 17408 halves
__device__ __align__(256) unsigned short g_Bt[2 * 2 * 6 * MATSZ];

// ---------------- PTX helpers (baseline sm_100-legal: ldmatrix + mma.sync) ----------------
__device__ __forceinline__ uint32_t smem_u32(const void* p) {
    uint32_t a;
    asm("{ .reg .u64 t; cvta.to.shared.u64 t, %1; cvt.u32.u64 %0, t; }" : "=r"(a) : "l"(p));
    return a;
}
__device__ __forceinline__ void ldm_x4(uint32_t& r0, uint32_t& r1, uint32_t& r2, uint32_t& r3, uint32_t addr) {
    asm volatile("ldmatrix.sync.aligned.m8n8.x4.shared.b16 {%0,%1,%2,%3}, [%4];"
                 : "=r"(r0), "=r"(r1), "=r"(r2), "=r"(r3) : "r"(addr));
}
__device__ __forceinline__ void ldm_x2(uint32_t& r0, uint32_t& r1, uint32_t addr) {
    asm volatile("ldmatrix.sync.aligned.m8n8.x2.shared.b16 {%0,%1}, [%2];"
                 : "=r"(r0), "=r"(r1) : "r"(addr));
}
__device__ __forceinline__ void mma_bf16(float* d, const uint32_t* a, const uint32_t* b) {
    asm volatile("mma.sync.aligned.m16n8k16.row.col.f32.bf16.bf16.f32 "
                 "{%0,%1,%2,%3}, {%4,%5,%6,%7}, {%8,%9}, {%0,%1,%2,%3};"
                 : "+f"(d[0]), "+f"(d[1]), "+f"(d[2]), "+f"(d[3])
                 : "r"(a[0]), "r"(a[1]), "r"(a[2]), "r"(a[3]), "r"(b[0]), "r"(b[1]));
}

// ---------------- weight prep: transpose + hi/lo split into padded [N][Kpad] ----------------
__global__ void wprep_k(const float* __restrict__ W, const float* __restrict__ Wloop, int layer)
{
    int r = blockIdx.x;
    unsigned short* oh = g_Bt + layer * (2 * 6 * MATSZ) + r * MATSZ;
    unsigned short* ol = oh + 6 * MATSZ;
    const float* src = (r < 5) ? (W + r * 16384) : Wloop;
    for (int idx = threadIdx.x; idx < 16384; idx += blockDim.x) {
        int n = idx >> 7, k = idx & 127;
        float x = src[k * 128 + n];
        __nv_bfloat16 h = __float2bfloat16(x);
        __nv_bfloat16 l = __float2bfloat16(x - __bfloat162float(h));
        oh[n * LPAD + k] = *(unsigned short*)&h;
        ol[n * LPAD + k] = *(unsigned short*)&l;
    }
}

// ---------------- fused relation GEMM (tensor cores via mma.sync bf16-split) ----------------
// 256 threads (8 warps, 4m x 2n), 256-row tile.
// SMEM: A_hi[256][136], A_lo[256][136], B_hi[128][136], B_lo[128][136]
#define MROWS 256
#define SA_HI 0
#define SA_LO 69632
#define SB_HI 139264
#define SB_LO 174080
#define SMEM_DYN 208896

__global__ void __launch_bounds__(256, 1) rgemm_k(const float* __restrict__ Aext,
                                                  const float* __restrict__ bias, int layer)
{
    extern __shared__ char dsm[];
    const float* A = (layer == 0) ? Aext : g_h1;
    uint32_t sbase = smem_u32(dsm);
    int tid = threadIdx.x;
    int w = tid >> 5, lane = tid & 31;
    int row0 = blockIdx.x * MROWS;
    const unsigned short* BtHi = g_Bt + layer * (2 * 6 * MATSZ);
    const unsigned short* BtLo = BtHi + 6 * MATSZ;

    // ---- convert A tile (256 rows x 128 cols) to hi/lo bf16 padded SMEM ----
    {
        uint32_t* ah = (uint32_t*)(dsm + SA_HI);
        uint32_t* al = (uint32_t*)(dsm + SA_LO);
        for (int i = tid; i < MROWS * 64; i += 256) {
            int n = i >> 6, kp = i & 63;
            int grow = row0 + n;
            uint32_t ph = 0u, pl = 0u;
            if (grow < Nn) {
                float2 x = *((const float2*)(A + (long long)grow * 128) + kp);
                __nv_bfloat16 h0 = __float2bfloat16(x.x);
                __nv_bfloat16 h1 = __float2bfloat16(x.y);
                __nv_bfloat16 l0 = __float2bfloat16(x.x - __bfloat162float(h0));
                __nv_bfloat16 l1 = __float2bfloat16(x.y - __bfloat162float(h1));
                ph = ((uint32_t)(*(unsigned short*)&h1) << 16) | (*(unsigned short*)&h0);
                pl = ((uint32_t)(*(unsigned short*)&l1) << 16) | (*(unsigned short*)&l0);
            }
            ah[n * (LPAD / 2) + kp] = ph;
            al[n * (LPAD / 2) + kp] = pl;
        }
    }

    // warp tiling: 4(m) x 2(n) warps, each 64(m) x 64(n)
    int wm0 = (w >> 1) * 64;
    int wn0 = (w & 1) * 64;
    int a_row = (lane & 15);
    int a_koff = (lane >> 4) << 3;
    int b_n = (lane & 7);
    int b_koff = ((lane >> 3) & 1) << 3;

    for (int r = 0; r < 6; r++) {
        __syncthreads();   // prior-iter SMEM B reads done before overwrite
        // copy B mat (hi+lo) L2 -> SMEM, raw (pre-padded layout)
        {
            const float4* shp = (const float4*)(BtHi + r * MATSZ);
            const float4* slp = (const float4*)(BtLo + r * MATSZ);
            float4* dh = (float4*)(dsm + SB_HI);
            float4* dl = (float4*)(dsm + SB_LO);
            for (int i = tid; i < MATSZ / 8; i += 256) { dh[i] = shp[i]; dl[i] = slp[i]; }
        }
        __syncthreads();

        float acc[4][8][4];
#pragma unroll
        for (int mi = 0; mi < 4; mi++)
#pragma unroll
            for (int nj = 0; nj < 8; nj++)
#pragma unroll
                for (int q = 0; q < 4; q++) acc[mi][nj][q] = 0.f;

#pragma unroll
        for (int s = 0; s < 3; s++) {
            uint32_t abase = sbase + ((s == 2) ? SA_LO : SA_HI);
            uint32_t bbase = sbase + ((s == 1) ? SB_LO : SB_HI);
#pragma unroll
            for (int kk = 0; kk < 8; kk++) {
                int k0 = kk * 16;
                uint32_t bfrag[8][2];
#pragma unroll
                for (int nj = 0; nj < 8; nj++) {
                    uint32_t addr = bbase + (uint32_t)(((wn0 + nj * 8 + b_n) * LPAD + k0 + b_koff) * 2);
                    ldm_x2(bfrag[nj][0], bfrag[nj][1], addr);
                }
                uint32_t afrag[4][4];
#pragma unroll
                for (int mi = 0; mi < 4; mi++) {
                    uint32_t addr = abase + (uint32_t)(((wm0 + mi * 16 + a_row) * LPAD + k0 + a_koff) * 2);
                    ldm_x4(afrag[mi][0], afrag[mi][1], afrag[mi][2], afrag[mi][3], addr);
                }
#pragma unroll
                for (int mi = 0; mi < 4; mi++)
#pragma unroll
                    for (int nj = 0; nj < 8; nj++)
                        mma_bf16(acc[mi][nj], afrag[mi], bfrag[nj]);
            }
        }

        // write out
        int qr = lane >> 2, qc = lane & 3;
        float* outbase = (r < 5) ? (g_hW + (long long)r * Nn * 128) : g_agg;
#pragma unroll
        for (int mi = 0; mi < 4; mi++) {
            int grow0 = row0 + wm0 + mi * 16 + qr;
#pragma unroll
            for (int half = 0; half < 2; half++) {
                int grow = grow0 + half * 8;
                if (grow < Nn) {
                    float* op = outbase + (long long)grow * 128;
#pragma unroll
                    for (int nj = 0; nj < 8; nj++) {
                        int col = wn0 + nj * 8 + qc * 2;
                        float2 v;
                        v.x = acc[mi][nj][half * 2 + 0];
                        v.y = acc[mi][nj][half * 2 + 1];
                        if (r == 5) { v.x += bias[col]; v.y += bias[col + 1]; }
                        *(float2*)(op + col) = v;
                    }
                }
            }
        }
    }
}

// ---------------- zero/init ----------------
__global__ void zinit_k(int both) {
    int t = threadIdx.x;
    if (t < 256) g_stats[t] = 0.f;
    if (both && t < 2) g_E[t] = 0.0;
}

// ---------------- small FFMA GEMM for disc (M=512) ----------------
// asel: 0=Aext  1=g_pos  2=g_sm ; rsel: 0=none 1=ext(ridx) 2=g_ridxP 3=g_ridxN
// csel: 0=g_fcx 1=g_aM 2=g_cX 3=g_rP 4=g_rN
__global__ void __launch_bounds__(256) gemm128_k(
    const float* __restrict__ Aext, int asel,
    const int* __restrict__ ridxExt, int rsel,
    const float* __restrict__ B, const float* __restrict__ bias, int csel)
{
    const float* A = (asel == 0) ? Aext : (asel == 1 ? g_pos : g_sm);
    const int* rowidx = (rsel == 0) ? (const int*)0
                      : (rsel == 1) ? ridxExt
                      : (rsel == 2) ? g_ridxP : g_ridxN;
    float* C = (csel == 0) ? g_fcx : (csel == 1) ? g_aM : (csel == 2) ? g_cX
             : (csel == 3) ? g_rP : g_rN;
    __shared__ float As[32][132];
    __shared__ float Bs[32][132];
    const int row0 = blockIdx.x * 128;
    const int tid = threadIdx.x;
    const int tx = tid & 15, ty = tid >> 4;
    float acc[8][8];
#pragma unroll
    for (int i = 0; i < 8; i++)
#pragma unroll
        for (int j = 0; j < 8; j++) acc[i][j] = 0.f;

    for (int kk = 0; kk < 128; kk += 32) {
#pragma unroll
        for (int i = 0; i < 4; i++) {
            int idx = tid + i * 256;
            int rw = idx >> 3;
            int c4 = idx & 7;
            int grow = row0 + rw;
            float4 v = make_float4(0.f, 0.f, 0.f, 0.f);
            if (grow < NEGO) {
                int ar = rowidx ? rowidx[grow] : grow;
                v = *(const float4*)(A + (long long)ar * 128 + kk + c4 * 4);
            }
            As[c4 * 4 + 0][rw] = v.x;
            As[c4 * 4 + 1][rw] = v.y;
            As[c4 * 4 + 2][rw] = v.z;
            As[c4 * 4 + 3][rw] = v.w;
        }
#pragma unroll
        for (int i = 0; i < 4; i++) {
            int idx = tid + i * 256;
            int rw = idx >> 5;
            int c4 = idx & 31;
            float4 v = *(const float4*)(B + (long long)(kk + rw) * 128 + c4 * 4);
            *(float4*)&Bs[rw][c4 * 4] = v;
        }
        __syncthreads();
#pragma unroll
        for (int k = 0; k < 32; k++) {
            float a[8], b[8];
#pragma unroll
            for (int i = 0; i < 8; i++) a[i] = As[k][ty * 8 + i];
#pragma unroll
            for (int j = 0; j < 8; j++) b[j] = Bs[k][tx * 8 + j];
#pragma unroll
            for (int i = 0; i < 8; i++)
#pragma unroll
                for (int j = 0; j < 8; j++) acc[i][j] += a[i] * b[j];
        }
        __syncthreads();
    }
#pragma unroll
    for (int i = 0; i < 8; i++) {
        int grow = row0 + ty * 8 + i;
        if (grow >= NEGO) continue;
#pragma unroll
        for (int j = 0; j < 8; j++) {
            int col = tx * 8 + j;
            float v = acc[i][j];
            if (bias) v += bias[col];
            C[(long long)grow * 128 + col] = v;
        }
    }
}

// ---------------- edge scatter: g_agg[dst] += g_hW[etype][src] ----------------
__global__ void __launch_bounds__(256) scatter_k(
    const int* __restrict__ src, const int* __restrict__ dst, const int* __restrict__ et)
{
    int gw = (int)((blockIdx.x * blockDim.x + threadIdx.x) >> 5);
    int lane = threadIdx.x & 31;
    if (gw >= Ee) return;
    int s = src[gw], d = dst[gw], r = et[gw];
    float4 v = *((const float4*)(g_hW + ((long long)r * Nn + s) * 128) + lane);
    float* q = g_agg + (long long)d * 128 + lane * 4;
    asm volatile("red.global.add.v4.f32 [%0], {%1,%2,%3,%4};"
                 :: "l"(q), "f"(v.x), "f"(v.y), "f"(v.z), "f"(v.w) : "memory");
}

// ---------------- BN stats over leaky_relu(g_agg): per-col sum & sumsq ----------------
__global__ void __launch_bounds__(256) bnstats_k()
{
    int col = threadIdx.x & 127;
    int half = threadIdx.x >> 7;
    float s = 0.f, s2 = 0.f;
    for (long long r = (long long)blockIdx.x * 2 + half; r < Nn; r += (long long)gridDim.x * 2) {
        float v = g_agg[r * 128 + col];
        v = v >= 0.f ? v : 0.01f * v;
        s += v; s2 += v * v;
    }
    __shared__ float sh[256], sh2[256];
    sh[threadIdx.x] = s; sh2[threadIdx.x] = s2;
    __syncthreads();
    if (half == 0) {
        atomicAdd(&g_stats[col], s + sh[col + 128]);
        atomicAdd(&g_stats[128 + col], s2 + sh2[col + 128]);
    }
}

// ---------------- BN apply + relu ----------------
__global__ void __launch_bounds__(256) bnapply_k(int layer)
{
    long long i = (long long)blockIdx.x * blockDim.x + threadIdx.x;
    if (i >= (long long)Nn * 32) return;
    float4* Y = (float4*)(layer == 0 ? g_h1 : g_pos);
    int c4 = (int)(i & 31);
    float4 x = ((const float4*)g_agg)[i];
    float o[4]; float in[4] = {x.x, x.y, x.z, x.w};
#pragma unroll
    for (int j = 0; j < 4; j++) {
        int col = c4 * 4 + j;
        float mean = g_stats[col] * (1.0f / Nn);
        float var = g_stats[128 + col] * (1.0f / Nn) - mean * mean;
        float v = in[j];
        v = v >= 0.f ? v : 0.01f * v;
        float y = (v - mean) * rsqrtf(var + 1e-5f);
        o[j] = y > 0.f ? y : 0.f;
    }
    Y[i] = make_float4(o[0], o[1], o[2], o[3]);
}

// ---------------- disc structure prep ----------------
__global__ void __launch_bounds__(512) discprep_k(
    const int* __restrict__ es, const int* __restrict__ ed,
    const int* __restrict__ ego, const int* __restrict__ perm)
{
    __shared__ unsigned adj[NEGO][16];
    __shared__ int spm[NEGO];
    __shared__ int rep[NEGO];
    int t = threadIdx.x;
#pragma unroll
    for (int w = 0; w < 16; w++) adj[t][w] = 0u;
    __syncthreads();
    for (int e = t; e < EEGO; e += 512) {
        int s = es[e], d = ed[e];
        if (s < d) atomicOr(&adj[d][s >> 5], 1u << (s & 31));
    }
    __syncthreads();
    int p = -1;
    int wj = t >> 5, bj = t & 31;
    unsigned m = bj ? (adj[t][wj] & ((1u << bj) - 1u)) : 0u;
    if (m) p = wj * 32 + 31 - __clz(m);
    for (int w = wj - 1; w >= 0 && p < 0; w--) {
        unsigned mm = adj[t][w];
        if (mm) p = w * 32 + 31 - __clz(mm);
    }
    spm[t] = p;
    g_pmax[t] = p;
    __syncthreads();
    if (t == 0) {
        for (int i = 0; i < NEGO; i++) {
            int pi = spm[i];
            rep[i] = (pi < 0) ? i : rep[pi];
        }
    }
    __syncthreads();
    int rid = ego[rep[t]];
    g_ridxP[t] = rid;
    g_ridxN[t] = perm[rid];
}

// ---------------- sequential snap_m recurrence ----------------
__global__ void __launch_bounds__(512) scan_k(
    const float* __restrict__ Wfc, const float* __restrict__ bfc)
{
    __shared__ float sp[128];
    __shared__ float red[512];
    __shared__ int pm[NEGO];
    int t = threadIdx.x;
    pm[t] = g_pmax[t];
    int col = t & 127;
    int q = t >> 7;
    __syncthreads();
    for (int i = 0; i < NEGO; i++) {
        int p = pm[i];
        if (p >= 0 && p != 1) {
            if (t < 128) sp[t] = g_sm[p * 128 + t];
            __syncthreads();
            float partial = 0.f;
            const float* wc = Wfc + col;
#pragma unroll
            for (int k = 0; k < 32; k++) partial += sp[q * 32 + k] * wc[(q * 32 + k) * 128];
            red[t] = partial;
        }
        __syncthreads();
        if (t < 128) {
            float v = 0.f;
            if (p >= 0) {
                float msg = (p == 1) ? g_fcx[128 + col]
                                     : (red[col] + red[col + 128] + red[col + 256] + red[col + 384] + bfc[col]);
                v = g_fcx[i * 128 + col] + msg;
                v = v > 0.f ? v : 0.f;
            }
            g_sm[i * 128 + col] = v;
        }
        __syncthreads();
    }
}

// ---------------- per-edge logits + JSD accumulation ----------------
__device__ __forceinline__ double softplus_d(double z) {
    return (z > 0.0) ? z + log1p(exp(-z)) : log1p(exp(z));
}

__global__ void __launch_bounds__(256) edgelogit_k(
    const int* __restrict__ es, const int* __restrict__ ed,
    const float* __restrict__ blin, const float* __restrict__ Wus,
    const float* __restrict__ bus)
{
    int gw = (int)((blockIdx.x * blockDim.x + threadIdx.x) >> 5);
    int lane = threadIdx.x & 31;
    if (gw >= EEGO) return;
    int s = es[gw], d = ed[gw];
    float lp = 0.f, ln = 0.f;
#pragma unroll
    for (int j = 0; j < 4; j++) {
        int c = lane * 4 + j;
        float base = g_aM[s * 128 + c] + g_cX[d * 128 + c] + blin[c];
        float w = Wus[c];
        float hp = base + g_rP[s * 128 + c]; hp = hp > 0.f ? hp : 0.f;
        float hn = base + g_rN[s * 128 + c]; hn = hn > 0.f ? hn : 0.f;
        lp += hp * w; ln += hn * w;
    }
#pragma unroll
    for (int o = 16; o; o >>= 1) {
        lp += __shfl_xor_sync(0xffffffffu, lp, o);
        ln += __shfl_xor_sync(0xffffffffu, ln, o);
    }
    if (lane == 0) {
        float bu = bus[0];
        double zp = (double)(lp + bu);
        double zn = (double)(ln + bu);
        atomicAdd(&g_E[0], LOG2C - softplus_d(-zp));
        atomicAdd(&g_E[1], softplus_d(-zn) + zn - LOG2C);
    }
}

__global__ void final_k(float* __restrict__ outp) {
    outp[0] = (float)((g_E[1] - g_E[0]) * (1.0 / (double)EEGO));
}

// ---------------- host ----------------
extern "C" void kernel_launch(void* const* d_in, const int* in_sizes, int n_in,
                              void* d_out, int out_size) {
    const float* features = (const float*)d_in[0];
    const float* W1     = (const float*)d_in[1];
    const float* Wloop1 = (const float*)d_in[2];
    const float* b1     = (const float*)d_in[3];
    const float* W2     = (const float*)d_in[4];
    const float* Wloop2 = (const float*)d_in[5];
    const float* b2     = (const float*)d_in[6];
    const float* Wfc    = (const float*)d_in[7];
    const float* bfc    = (const float*)d_in[8];
    const float* Wlin   = (const float*)d_in[9];
    const float* blin   = (const float*)d_in[10];
    const float* Wus    = (const float*)d_in[11];
    const float* bus    = (const float*)d_in[12];
    const int* src      = (const int*)d_in[13];
    const int* dst      = (const int*)d_in[14];
    const int* etype    = (const int*)d_in[15];
    const int* perm     = (const int*)d_in[16];
    const int* ego_ids  = (const int*)d_in[17];
    const int* ego_src  = (const int*)d_in[18];
    const int* ego_dst  = (const int*)d_in[19];

    cudaFuncSetAttribute(rgemm_k, cudaFuncAttributeMaxDynamicSharedMemorySize, SMEM_DYN);

    const int mt = (Nn + MROWS - 1) / MROWS;   // 391 row tiles
    const int scat_blocks = (Ee * 32) / 256;   // 100000
    const int bna_blocks = (Nn * 32 + 255) / 256;

    zinit_k<<<1, 256>>>(1);
    wprep_k<<<6, 256>>>(W1, Wloop1, 0);
    wprep_k<<<6, 256>>>(W2, Wloop2, 1);

    // ---- encoder layer 1 ----
    rgemm_k<<<mt, 256, SMEM_DYN>>>(features, b1, 0);
    scatter_k<<<scat_blocks, 256>>>(src, dst, etype);
    bnstats_k<<<512, 256>>>();
    bnapply_k<<<bna_blocks, 256>>>(0);

    // ---- encoder layer 2 ----
    zinit_k<<<1, 256>>>(0);
    rgemm_k<<<mt, 256, SMEM_DYN>>>(features, b2, 1);
    scatter_k<<<scat_blocks, 256>>>(src, dst, etype);
    bnstats_k<<<512, 256>>>();
    bnapply_k<<<bna_blocks, 256>>>(1);

    // ---- discriminator ----
    discprep_k<<<1, 512>>>(ego_src, ego_dst, ego_ids, perm);
    gemm128_k<<<4, 256>>>(features, 0, ego_ids, 1, Wfc, bfc, 0);            // fcx
    scan_k<<<1, 512>>>(Wfc, bfc);
    gemm128_k<<<4, 256>>>((const float*)0, 2, (const int*)0, 0, Wlin + 128 * 128, (const float*)0, 1); // aM from sm
    gemm128_k<<<4, 256>>>(features, 0, ego_ids, 1, Wlin + 256 * 128, (const float*)0, 2);              // cX
    gemm128_k<<<4, 256>>>((const float*)0, 1, (const int*)0, 2, Wlin, (const float*)0, 3);             // rP
    gemm128_k<<<4, 256>>>((const float*)0, 1, (const int*)0, 3, Wlin, (const float*)0, 4);             // rN
    edgelogit_k<<<512, 256>>>(ego_src, ego_dst, blin, Wus, bus);
    final_k<<<1, 1>>>((float*)d_out);
}

// round 8
// speedup vs baseline: 1.9672x; 1.0891x over previous
#include <cuda_runtime.h>
#include <cuda_bf16.h>
#include <stdint.h>
#include <math.h>

#define Nn 100000
#define Ee 800000
#define NEGO 512
#define EEGO 4096
#define RR 5
#define HH 128
#define LOG2C 0.6931471805599453

// ---------------- scratch (device globals; no allocation allowed) ----------------
__device__ float g_hW[(size_t)RR * Nn * HH];   // 256 MB
__device__ float g_agg[(size_t)Nn * HH];       // 51 MB
__device__ float g_h1[(size_t)Nn * HH];        // 51 MB
__device__ float g_pos[(size_t)Nn * HH];       // 51 MB
__device__ float g_stats[256];
__device__ float g_fcx[NEGO * HH];
__device__ float g_sm[NEGO * HH];
__device__ float g_aM[NEGO * HH];
__device__ float g_cX[NEGO * HH];
__device__ float g_rP[NEGO * HH];
__device__ float g_rN[NEGO * HH];
__device__ int   g_pmax[NEGO];
__device__ int   g_ridxP[NEGO];
__device__ int   g_ridxN[NEGO];
__device__ int   g_order[NEGO];
__device__ int   g_lvls[NEGO + 1];
__device__ int   g_nlev;
__device__ double g_E[2];
// transposed bf16 weight images [N=128][Kpad=136] per mat:
// layout: [layer(2)][half(2: hi,lo)][mat(6)][17408]
#define LPAD 136
#define MATSZ (128 * LPAD)   // 17408 halves
__device__ __align__(256) unsigned short g_Bt[2 * 2 * 6 * MATSZ];

// ---------------- PTX helpers (baseline sm_100-legal) ----------------
__device__ __forceinline__ uint32_t smem_u32(const void* p) {
    uint32_t a;
    asm("{ .reg .u64 t; cvta.to.shared.u64 t, %1; cvt.u32.u64 %0, t; }" : "=r"(a) : "l"(p));
    return a;
}
__device__ __forceinline__ void ldm_x4(uint32_t& r0, uint32_t& r1, uint32_t& r2, uint32_t& r3, uint32_t addr) {
    asm volatile("ldmatrix.sync.aligned.m8n8.x4.shared.b16 {%0,%1,%2,%3}, [%4];"
                 : "=r"(r0), "=r"(r1), "=r"(r2), "=r"(r3) : "r"(addr));
}
__device__ __forceinline__ void ldm_x2(uint32_t& r0, uint32_t& r1, uint32_t addr) {
    asm volatile("ldmatrix.sync.aligned.m8n8.x2.shared.b16 {%0,%1}, [%2];"
                 : "=r"(r0), "=r"(r1) : "r"(addr));
}
__device__ __forceinline__ void mma_bf16(float* d, const uint32_t* a, const uint32_t* b) {
    asm volatile("mma.sync.aligned.m16n8k16.row.col.f32.bf16.bf16.f32 "
                 "{%0,%1,%2,%3}, {%4,%5,%6,%7}, {%8,%9}, {%0,%1,%2,%3};"
                 : "+f"(d[0]), "+f"(d[1]), "+f"(d[2]), "+f"(d[3])
                 : "r"(a[0]), "r"(a[1]), "r"(a[2]), "r"(a[3]), "r"(b[0]), "r"(b[1]));
}
__device__ __forceinline__ void cpa16(uint32_t smaddr, const void* g) {
    asm volatile("cp.async.cg.shared.global [%0], [%1], 16;" :: "r"(smaddr), "l"(g) : "memory");
}
__device__ __forceinline__ void cpa_commit() { asm volatile("cp.async.commit_group;" ::: "memory"); }
__device__ __forceinline__ void cpa_wait0() { asm volatile("cp.async.wait_group 0;" ::: "memory"); }

// ---------------- weight prep: transpose + hi/lo split into padded [N][Kpad] ----------------
__global__ void wprep_k(const float* __restrict__ W, const float* __restrict__ Wloop, int layer)
{
    int r = blockIdx.x;
    unsigned short* oh = g_Bt + layer * (2 * 6 * MATSZ) + r * MATSZ;
    unsigned short* ol = oh + 6 * MATSZ;
    const float* src = (r < 5) ? (W + r * 16384) : Wloop;
    for (int idx = threadIdx.x; idx < 16384; idx += blockDim.x) {
        int n = idx >> 7, k = idx & 127;
        float x = src[k * 128 + n];
        __nv_bfloat16 h = __float2bfloat16(x);
        __nv_bfloat16 l = __float2bfloat16(x - __bfloat162float(h));
        oh[n * LPAD + k] = *(unsigned short*)&h;
        ol[n * LPAD + k] = *(unsigned short*)&l;
    }
}

// ---------------- fused relation GEMM (mma.sync bf16-split, cp.async B prefetch) ----------------
#define MROWS 256
#define SA_HI 0
#define SA_LO 69632
#define SB_HI 139264
#define SB_LO 174080
#define SMEM_DYN 208896

__global__ void __launch_bounds__(256, 1) rgemm_k(const float* __restrict__ Aext,
                                                  const float* __restrict__ bias, int layer)
{
    extern __shared__ char dsm[];
    const float* A = (layer == 0) ? Aext : g_h1;
    uint32_t sbase = smem_u32(dsm);
    int tid = threadIdx.x;
    int w = tid >> 5, lane = tid & 31;
    int row0 = blockIdx.x * MROWS;
    const unsigned short* BtHi = g_Bt + layer * (2 * 6 * MATSZ);
    const unsigned short* BtLo = BtHi + 6 * MATSZ;

    // ---- issue cp.async for B(r=0) first, then convert A while it flies ----
    {
        const char* shp = (const char*)(BtHi);
        const char* slp = (const char*)(BtLo);
#pragma unroll
        for (int i = 0; i < 17; i++) {
            int off = (tid + i * 256) * 16;
            if (off < MATSZ * 2) {
                cpa16(sbase + SB_HI + off, shp + off);
                cpa16(sbase + SB_LO + off, slp + off);
            }
        }
        cpa_commit();
    }

    // ---- convert A tile (256 rows x 128 cols) to hi/lo bf16 padded SMEM ----
    {
        uint32_t* ah = (uint32_t*)(dsm + SA_HI);
        uint32_t* al = (uint32_t*)(dsm + SA_LO);
        for (int i = tid; i < MROWS * 64; i += 256) {
            int n = i >> 6, kp = i & 63;
            int grow = row0 + n;
            uint32_t ph = 0u, pl = 0u;
            if (grow < Nn) {
                float2 x = *((const float2*)(A + (long long)grow * 128) + kp);
                __nv_bfloat16 h0 = __float2bfloat16(x.x);
                __nv_bfloat16 h1 = __float2bfloat16(x.y);
                __nv_bfloat16 l0 = __float2bfloat16(x.x - __bfloat162float(h0));
                __nv_bfloat16 l1 = __float2bfloat16(x.y - __bfloat162float(h1));
                ph = ((uint32_t)(*(unsigned short*)&h1) << 16) | (*(unsigned short*)&h0);
                pl = ((uint32_t)(*(unsigned short*)&l1) << 16) | (*(unsigned short*)&l0);
            }
            ah[n * (LPAD / 2) + kp] = ph;
            al[n * (LPAD / 2) + kp] = pl;
        }
    }
    cpa_wait0();
    __syncthreads();

    // warp tiling: 4(m) x 2(n) warps, each 64(m) x 64(n)
    int wm0 = (w >> 1) * 64;
    int wn0 = (w & 1) * 64;
    int a_row = (lane & 15);
    int a_koff = (lane >> 4) << 3;
    int b_n = (lane & 7);
    int b_koff = ((lane >> 3) & 1) << 3;

    for (int r = 0; r < 6; r++) {
        float acc[4][8][4];
#pragma unroll
        for (int mi = 0; mi < 4; mi++)
#pragma unroll
            for (int nj = 0; nj < 8; nj++)
#pragma unroll
                for (int q = 0; q < 4; q++) acc[mi][nj][q] = 0.f;

#pragma unroll
        for (int s = 0; s < 3; s++) {
            uint32_t abase = sbase + ((s == 2) ? SA_LO : SA_HI);
            uint32_t bbase = sbase + ((s == 1) ? SB_LO : SB_HI);
#pragma unroll
            for (int kk = 0; kk < 8; kk++) {
                int k0 = kk * 16;
                uint32_t bfrag[8][2];
#pragma unroll
                for (int nj = 0; nj < 8; nj++) {
                    uint32_t addr = bbase + (uint32_t)(((wn0 + nj * 8 + b_n) * LPAD + k0 + b_koff) * 2);
                    ldm_x2(bfrag[nj][0], bfrag[nj][1], addr);
                }
                uint32_t afrag[4][4];
#pragma unroll
                for (int mi = 0; mi < 4; mi++) {
                    uint32_t addr = abase + (uint32_t)(((wm0 + mi * 16 + a_row) * LPAD + k0 + a_koff) * 2);
                    ldm_x4(afrag[mi][0], afrag[mi][1], afrag[mi][2], afrag[mi][3], addr);
                }
#pragma unroll
                for (int mi = 0; mi < 4; mi++)
#pragma unroll
                    for (int nj = 0; nj < 8; nj++)
                        mma_bf16(acc[mi][nj], afrag[mi], bfrag[nj]);
            }
        }
        __syncthreads();   // all MMAs done reading B(r) -> buffer free

        // prefetch B(r+1) under the epilogue
        if (r < 5) {
            const char* shp = (const char*)(BtHi + (r + 1) * MATSZ);
            const char* slp = (const char*)(BtLo + (r + 1) * MATSZ);
#pragma unroll
            for (int i = 0; i < 17; i++) {
                int off = (tid + i * 256) * 16;
                if (off < MATSZ * 2) {
                    cpa16(sbase + SB_HI + off, shp + off);
                    cpa16(sbase + SB_LO + off, slp + off);
                }
            }
            cpa_commit();
        }

        // epilogue writes (overlap with cp.async)
        int qr = lane >> 2, qc = lane & 3;
        float* outbase = (r < 5) ? (g_hW + (long long)r * Nn * 128) : g_agg;
#pragma unroll
        for (int mi = 0; mi < 4; mi++) {
            int grow0 = row0 + wm0 + mi * 16 + qr;
#pragma unroll
            for (int half = 0; half < 2; half++) {
                int grow = grow0 + half * 8;
                if (grow < Nn) {
                    float* op = outbase + (long long)grow * 128;
#pragma unroll
                    for (int nj = 0; nj < 8; nj++) {
                        int col = wn0 + nj * 8 + qc * 2;
                        float2 v;
                        v.x = acc[mi][nj][half * 2 + 0];
                        v.y = acc[mi][nj][half * 2 + 1];
                        if (r == 5) { v.x += bias[col]; v.y += bias[col + 1]; }
                        *(float2*)(op + col) = v;
                    }
                }
            }
        }
        if (r < 5) cpa_wait0();
        __syncthreads();
    }
}

// ---------------- zero/init ----------------
__global__ void zinit_k(int both) {
    int t = threadIdx.x;
    if (t < 256) g_stats[t] = 0.f;
    if (both && t < 2) g_E[t] = 0.0;
}

// ---------------- small FFMA GEMM for disc (M=512) ----------------
__global__ void __launch_bounds__(256) gemm128_k(
    const float* __restrict__ Aext, int asel,
    const int* __restrict__ ridxExt, int rsel,
    const float* __restrict__ B, const float* __restrict__ bias, int csel)
{
    const float* A = (asel == 0) ? Aext : (asel == 1 ? g_pos : g_sm);
    const int* rowidx = (rsel == 0) ? (const int*)0
                      : (rsel == 1) ? ridxExt
                      : (rsel == 2) ? g_ridxP : g_ridxN;
    float* C = (csel == 0) ? g_fcx : (csel == 1) ? g_aM : (csel == 2) ? g_cX
             : (csel == 3) ? g_rP : g_rN;
    __shared__ float As[32][132];
    __shared__ float Bs[32][132];
    const int row0 = blockIdx.x * 128;
    const int tid = threadIdx.x;
    const int tx = tid & 15, ty = tid >> 4;
    float acc[8][8];
#pragma unroll
    for (int i = 0; i < 8; i++)
#pragma unroll
        for (int j = 0; j < 8; j++) acc[i][j] = 0.f;

    for (int kk = 0; kk < 128; kk += 32) {
#pragma unroll
        for (int i = 0; i < 4; i++) {
            int idx = tid + i * 256;
            int rw = idx >> 3;
            int c4 = idx & 7;
            int grow = row0 + rw;
            float4 v = make_float4(0.f, 0.f, 0.f, 0.f);
            if (grow < NEGO) {
                int ar = rowidx ? rowidx[grow] : grow;
                v = *(const float4*)(A + (long long)ar * 128 + kk + c4 * 4);
            }
            As[c4 * 4 + 0][rw] = v.x;
            As[c4 * 4 + 1][rw] = v.y;
            As[c4 * 4 + 2][rw] = v.z;
            As[c4 * 4 + 3][rw] = v.w;
        }
#pragma unroll
        for (int i = 0; i < 4; i++) {
            int idx = tid + i * 256;
            int rw = idx >> 5;
            int c4 = idx & 31;
            float4 v = *(const float4*)(B + (long long)(kk + rw) * 128 + c4 * 4);
            *(float4*)&Bs[rw][c4 * 4] = v;
        }
        __syncthreads();
#pragma unroll
        for (int k = 0; k < 32; k++) {
            float a[8], b[8];
#pragma unroll
            for (int i = 0; i < 8; i++) a[i] = As[k][ty * 8 + i];
#pragma unroll
            for (int j = 0; j < 8; j++) b[j] = Bs[k][tx * 8 + j];
#pragma unroll
            for (int i = 0; i < 8; i++)
#pragma unroll
                for (int j = 0; j < 8; j++) acc[i][j] += a[i] * b[j];
        }
        __syncthreads();
    }
#pragma unroll
    for (int i = 0; i < 8; i++) {
        int grow = row0 + ty * 8 + i;
        if (grow >= NEGO) continue;
#pragma unroll
        for (int j = 0; j < 8; j++) {
            int col = tx * 8 + j;
            float v = acc[i][j];
            if (bias) v += bias[col];
            C[(long long)grow * 128 + col] = v;
        }
    }
}

// ---------------- edge scatter: g_agg[dst] += g_hW[etype][src] ----------------
__global__ void __launch_bounds__(256) scatter_k(
    const int* __restrict__ src, const int* __restrict__ dst, const int* __restrict__ et)
{
    int gw = (int)((blockIdx.x * blockDim.x + threadIdx.x) >> 5);
    int lane = threadIdx.x & 31;
    if (gw >= Ee) return;
    int s = src[gw], d = dst[gw], r = et[gw];
    float4 v = *((const float4*)(g_hW + ((long long)r * Nn + s) * 128) + lane);
    float* q = g_agg + (long long)d * 128 + lane * 4;
    asm volatile("red.global.add.v4.f32 [%0], {%1,%2,%3,%4};"
                 :: "l"(q), "f"(v.x), "f"(v.y), "f"(v.z), "f"(v.w) : "memory");
}

// ---------------- BN stats over leaky_relu(g_agg): per-col sum & sumsq ----------------
__global__ void __launch_bounds__(256) bnstats_k()
{
    int col = threadIdx.x & 127;
    int half = threadIdx.x >> 7;
    float s = 0.f, s2 = 0.f;
    for (long long r = (long long)blockIdx.x * 2 + half; r < Nn; r += (long long)gridDim.x * 2) {
        float v = g_agg[r * 128 + col];
        v = v >= 0.f ? v : 0.01f * v;
        s += v; s2 += v * v;
    }
    __shared__ float sh[256], sh2[256];
    sh[threadIdx.x] = s; sh2[threadIdx.x] = s2;
    __syncthreads();
    if (half == 0) {
        atomicAdd(&g_stats[col], s + sh[col + 128]);
        atomicAdd(&g_stats[128 + col], s2 + sh2[col + 128]);
    }
}

// ---------------- BN apply + relu ----------------
__global__ void __launch_bounds__(256) bnapply_k(int layer)
{
    long long i = (long long)blockIdx.x * blockDim.x + threadIdx.x;
    if (i >= (long long)Nn * 32) return;
    float4* Y = (float4*)(layer == 0 ? g_h1 : g_pos);
    int c4 = (int)(i & 31);
    float4 x = ((const float4*)g_agg)[i];
    float o[4]; float in[4] = {x.x, x.y, x.z, x.w};
#pragma unroll
    for (int j = 0; j < 4; j++) {
        int col = c4 * 4 + j;
        float mean = g_stats[col] * (1.0f / Nn);
        float var = g_stats[128 + col] * (1.0f / Nn) - mean * mean;
        float v = in[j];
        v = v >= 0.f ? v : 0.01f * v;
        float y = (v - mean) * rsqrtf(var + 1e-5f);
        o[j] = y > 0.f ? y : 0.f;
    }
    Y[i] = make_float4(o[0], o[1], o[2], o[3]);
}

// ---------------- disc structure prep (+ scan levelization) ----------------
__global__ void __launch_bounds__(512) discprep_k(
    const int* __restrict__ es, const int* __restrict__ ed,
    const int* __restrict__ ego, const int* __restrict__ perm)
{
    __shared__ unsigned adj[NEGO][16];
    __shared__ int spm[NEGO];
    __shared__ int rep[NEGO];
    int t = threadIdx.x;
#pragma unroll
    for (int w = 0; w < 16; w++) adj[t][w] = 0u;
    __syncthreads();
    for (int e = t; e < EEGO; e += 512) {
        int s = es[e], d = ed[e];
        if (s < d) atomicOr(&adj[d][s >> 5], 1u << (s & 31));
    }
    __syncthreads();
    int p = -1;
    int wj = t >> 5, bj = t & 31;
    unsigned m = bj ? (adj[t][wj] & ((1u << bj) - 1u)) : 0u;
    if (m) p = wj * 32 + 31 - __clz(m);
    for (int w = wj - 1; w >= 0 && p < 0; w--) {
        unsigned mm = adj[t][w];
        if (mm) p = w * 32 + 31 - __clz(mm);
    }
    spm[t] = p;
    g_pmax[t] = p;
    __syncthreads();
    if (t == 0) {
        for (int i = 0; i < NEGO; i++) {
            int pi = spm[i];
            rep[i] = (pi < 0) ? i : rep[pi];
        }
        // levelization: level[i] = 0 if p<0 or p==1 (no sm dependency), else level[p]+1
        int lev[NEGO];
        int cnt[NEGO + 1];
        for (int i = 0; i <= NEGO; i++) cnt[i] = 0;
        int maxl = 0;
        for (int i = 0; i < NEGO; i++) {
            int pi = spm[i];
            int l = (pi < 0 || pi == 1) ? 0 : lev[pi] + 1;
            lev[i] = l;
            cnt[l]++;
            if (l > maxl) maxl = l;
        }
        int run = 0;
        for (int l = 0; l <= maxl; l++) { g_lvls[l] = run; int c0 = cnt[l]; cnt[l] = run; run += c0; }
        g_lvls[maxl + 1] = run;
        for (int i = 0; i < NEGO; i++) g_order[cnt[lev[i]]++] = i;
        g_nlev = maxl + 1;
    }
    __syncthreads();
    int rid = ego[rep[t]];
    g_ridxP[t] = rid;
    g_ridxN[t] = perm[rid];
}

// ---------------- levelized snap_m recurrence ----------------
// dyn smem: Wsh[128][128] f32 (64KB) + spb[4][128] f32 (2KB)
#define SCAN2_SMEM (16384 * 4 + 512 * 4)
__global__ void __launch_bounds__(512) scan2_k(
    const float* __restrict__ Wfc, const float* __restrict__ bfc)
{
    extern __shared__ float ssc[];
    float* Wsh = ssc;           // [k*128 + col]
    float* spb = ssc + 16384;   // [g*128 + k]
    int t = threadIdx.x, g = t >> 7, c = t & 127;
    for (int i = t; i < 16384; i += 512) Wsh[i] = Wfc[i];   // Wfc is [k][col] row-major already
    __syncthreads();
    float bfcc = bfc[c];
    float fcx1 = g_fcx[128 + c];
    int nlev = g_nlev;
    for (int L = 0; L < nlev; L++) {
        int s0 = g_lvls[L], s1 = g_lvls[L + 1];
        for (int idx = s0 + g; idx < s1; idx += 4) {
            int i = g_order[idx];
            int p = g_pmax[i];
            float v;
            if (p < 0) {
                v = 0.f;
            } else if (p == 1) {
                v = g_fcx[i * 128 + c] + fcx1;
                v = v > 0.f ? v : 0.f;
            } else {
                spb[g * 128 + c] = g_sm[p * 128 + c];
                asm volatile("bar.sync %0, 128;" :: "r"(g + 1) : "memory");
                float acc = bfcc;
#pragma unroll 8
                for (int k = 0; k < 128; k++) acc += spb[g * 128 + k] * Wsh[k * 128 + c];
                v = g_fcx[i * 128 + c] + acc;
                v = v > 0.f ? v : 0.f;
                asm volatile("bar.sync %0, 128;" :: "r"(g + 1) : "memory");
            }
            g_sm[i * 128 + c] = v;
        }
        __syncthreads();   // level boundary: sm writes visible block-wide
    }
}

// ---------------- per-edge logits + JSD accumulation ----------------
__device__ __forceinline__ double softplus_d(double z) {
    return (z > 0.0) ? z + log1p(exp(-z)) : log1p(exp(z));
}

__global__ void __launch_bounds__(256) edgelogit_k(
    const int* __restrict__ es, const int* __restrict__ ed,
    const float* __restrict__ blin, const float* __restrict__ Wus,
    const float* __restrict__ bus)
{
    int gw = (int)((blockIdx.x * blockDim.x + threadIdx.x) >> 5);
    int lane = threadIdx.x & 31;
    if (gw >= EEGO) return;
    int s = es[gw], d = ed[gw];
    float lp = 0.f, ln = 0.f;
#pragma unroll
    for (int j = 0; j < 4; j++) {
        int c = lane * 4 + j;
        float base = g_aM[s * 128 + c] + g_cX[d * 128 + c] + blin[c];
        float w = Wus[c];
        float hp = base + g_rP[s * 128 + c]; hp = hp > 0.f ? hp : 0.f;
        float hn = base + g_rN[s * 128 + c]; hn = hn > 0.f ? hn : 0.f;
        lp += hp * w; ln += hn * w;
    }
#pragma unroll
    for (int o = 16; o; o >>= 1) {
        lp += __shfl_xor_sync(0xffffffffu, lp, o);
        ln += __shfl_xor_sync(0xffffffffu, ln, o);
    }
    if (lane == 0) {
        float bu = bus[0];
        double zp = (double)(lp + bu);
        double zn = (double)(ln + bu);
        atomicAdd(&g_E[0], LOG2C - softplus_d(-zp));
        atomicAdd(&g_E[1], softplus_d(-zn) + zn - LOG2C);
    }
}

__global__ void final_k(float* __restrict__ outp) {
    outp[0] = (float)((g_E[1] - g_E[0]) * (1.0 / (double)EEGO));
}

// ---------------- host ----------------
extern "C" void kernel_launch(void* const* d_in, const int* in_sizes, int n_in,
                              void* d_out, int out_size) {
    const float* features = (const float*)d_in[0];
    const float* W1     = (const float*)d_in[1];
    const float* Wloop1 = (const float*)d_in[2];
    const float* b1     = (const float*)d_in[3];
    const float* W2     = (const float*)d_in[4];
    const float* Wloop2 = (const float*)d_in[5];
    const float* b2     = (const float*)d_in[6];
    const float* Wfc    = (const float*)d_in[7];
    const float* bfc    = (const float*)d_in[8];
    const float* Wlin   = (const float*)d_in[9];
    const float* blin   = (const float*)d_in[10];
    const float* Wus    = (const float*)d_in[11];
    const float* bus    = (const float*)d_in[12];
    const int* src      = (const int*)d_in[13];
    const int* dst      = (const int*)d_in[14];
    const int* etype    = (const int*)d_in[15];
    const int* perm     = (const int*)d_in[16];
    const int* ego_ids  = (const int*)d_in[17];
    const int* ego_src  = (const int*)d_in[18];
    const int* ego_dst  = (const int*)d_in[19];

    cudaFuncSetAttribute(rgemm_k, cudaFuncAttributeMaxDynamicSharedMemorySize, SMEM_DYN);
    cudaFuncSetAttribute(scan2_k, cudaFuncAttributeMaxDynamicSharedMemorySize, SCAN2_SMEM);

    const int mt = (Nn + MROWS - 1) / MROWS;   // 391 row tiles
    const int scat_blocks = (Ee * 32) / 256;   // 100000
    const int bna_blocks = (Nn * 32 + 255) / 256;

    zinit_k<<<1, 256>>>(1);
    wprep_k<<<6, 256>>>(W1, Wloop1, 0);
    wprep_k<<<6, 256>>>(W2, Wloop2, 1);

    // ---- encoder layer 1 ----
    rgemm_k<<<mt, 256, SMEM_DYN>>>(features, b1, 0);
    scatter_k<<<scat_blocks, 256>>>(src, dst, etype);
    bnstats_k<<<512, 256>>>();
    bnapply_k<<<bna_blocks, 256>>>(0);

    // ---- encoder layer 2 ----
    zinit_k<<<1, 256>>>(0);
    rgemm_k<<<mt, 256, SMEM_DYN>>>(features, b2, 1);
    scatter_k<<<scat_blocks, 256>>>(src, dst, etype);
    bnstats_k<<<512, 256>>>();
    bnapply_k<<<bna_blocks, 256>>>(1);

    // ---- discriminator ----
    discprep_k<<<1, 512>>>(ego_src, ego_dst, ego_ids, perm);
    gemm128_k<<<4, 256>>>(features, 0, ego_ids, 1, Wfc, bfc, 0);            // fcx
    scan2_k<<<1, 512, SCAN2_SMEM>>>(Wfc, bfc);
    gemm128_k<<<4, 256>>>((const float*)0, 2, (const int*)0, 0, Wlin + 128 * 128, (const float*)0, 1); // aM from sm
    gemm128_k<<<4, 256>>>(features, 0, ego_ids, 1, Wlin + 256 * 128, (const float*)0, 2);              // cX
    gemm128_k<<<4, 256>>>((const float*)0, 1, (const int*)0, 2, Wlin, (const float*)0, 3);             // rP
    gemm128_k<<<4, 256>>>((const float*)0, 1, (const int*)0, 3, Wlin, (const float*)0, 4);             // rN
    edgelogit_k<<<512, 256>>>(ego_src, ego_dst, blin, Wus, bus);
    final_k<<<1, 1>>>((float*)d_out);
}

// round 9
// speedup vs baseline: 2.1942x; 1.1154x over previous
#include <cuda_runtime.h>
#include <cuda_bf16.h>
#include <stdint.h>
#include <math.h>

#define Nn 100000
#define Ee 800000
#define NEGO 512
#define EEGO 4096
#define RR 5
#define HH 128
#define LOG2C 0.6931471805599453

// ---------------- scratch (device globals; no allocation allowed) ----------------
__device__ float g_hW[(size_t)RR * Nn * HH];   // 256 MB
__device__ float g_agg[(size_t)Nn * HH];       // 51 MB
__device__ float g_h1[(size_t)Nn * HH];        // 51 MB
__device__ float g_pos[(size_t)Nn * HH];       // 51 MB
__device__ float g_stats[256];
__device__ float g_fcx[NEGO * HH];
__device__ float g_sm[NEGO * HH];
__device__ float g_aM[NEGO * HH];
__device__ float g_cX[NEGO * HH];
__device__ float g_rP[NEGO * HH];
__device__ float g_rN[NEGO * HH];
__device__ int   g_pmax[NEGO];
__device__ int   g_ridxP[NEGO];
__device__ int   g_ridxN[NEGO];
__device__ int   g_order[NEGO];
__device__ int   g_lvls[NEGO + 1];
__device__ int   g_nlev;
__device__ double g_E[2];
// transposed bf16 weight images [N=128][Kpad=136] per mat:
// layout: [layer(2)][half(2: hi,lo)][mat(6)][17408]
#define LPAD 136
#define MATSZ (128 * LPAD)   // 17408 halves
__device__ __align__(256) unsigned short g_Bt[2 * 2 * 6 * MATSZ];

// ---------------- PTX helpers (baseline sm_100-legal) ----------------
__device__ __forceinline__ uint32_t smem_u32(const void* p) {
    uint32_t a;
    asm("{ .reg .u64 t; cvta.to.shared.u64 t, %1; cvt.u32.u64 %0, t; }" : "=r"(a) : "l"(p));
    return a;
}
__device__ __forceinline__ void ldm_x4(uint32_t& r0, uint32_t& r1, uint32_t& r2, uint32_t& r3, uint32_t addr) {
    asm volatile("ldmatrix.sync.aligned.m8n8.x4.shared.b16 {%0,%1,%2,%3}, [%4];"
                 : "=r"(r0), "=r"(r1), "=r"(r2), "=r"(r3) : "r"(addr));
}
__device__ __forceinline__ void mma_bf16(float* d, const uint32_t* a, const uint32_t* b) {
    asm volatile("mma.sync.aligned.m16n8k16.row.col.f32.bf16.bf16.f32 "
                 "{%0,%1,%2,%3}, {%4,%5,%6,%7}, {%8,%9}, {%0,%1,%2,%3};"
                 : "+f"(d[0]), "+f"(d[1]), "+f"(d[2]), "+f"(d[3])
                 : "r"(a[0]), "r"(a[1]), "r"(a[2]), "r"(a[3]), "r"(b[0]), "r"(b[1]));
}
__device__ __forceinline__ void cpa16(uint32_t smaddr, const void* g) {
    asm volatile("cp.async.cg.shared.global [%0], [%1], 16;" :: "r"(smaddr), "l"(g) : "memory");
}
__device__ __forceinline__ void cpa_commit() { asm volatile("cp.async.commit_group;" ::: "memory"); }
__device__ __forceinline__ void cpa_wait0() { asm volatile("cp.async.wait_group 0;" ::: "memory"); }

// ---------------- weight prep: transpose + hi/lo split into padded [N][Kpad] ----------------
// grid (6 mats, 4 chunks)
__global__ void wprep_k(const float* __restrict__ W, const float* __restrict__ Wloop, int layer)
{
    int r = blockIdx.x;
    unsigned short* oh = g_Bt + layer * (2 * 6 * MATSZ) + r * MATSZ;
    unsigned short* ol = oh + 6 * MATSZ;
    const float* src = (r < 5) ? (W + r * 16384) : Wloop;
    int base = blockIdx.y * 4096;
    for (int idx = base + threadIdx.x; idx < base + 4096; idx += blockDim.x) {
        int n = idx >> 7, k = idx & 127;
        float x = src[k * 128 + n];
        __nv_bfloat16 h = __float2bfloat16(x);
        __nv_bfloat16 l = __float2bfloat16(x - __bfloat162float(h));
        oh[n * LPAD + k] = *(unsigned short*)&h;
        ol[n * LPAD + k] = *(unsigned short*)&l;
    }
}

// ---------------- fused relation GEMM (mma.sync bf16-split, cp.async B prefetch) ----------------
#define MROWS 256
#define SA_HI 0
#define SA_LO 69632
#define SB_HI 139264
#define SB_LO 174080
#define SMEM_DYN 208896

__global__ void __launch_bounds__(256, 1) rgemm_k(const float* __restrict__ Aext,
                                                  const float* __restrict__ bias, int layer)
{
    extern __shared__ char dsm[];
    const float* A = (layer == 0) ? Aext : g_h1;
    uint32_t sbase = smem_u32(dsm);
    int tid = threadIdx.x;
    int w = tid >> 5, lane = tid & 31;
    int row0 = blockIdx.x * MROWS;
    const unsigned short* BtHi = g_Bt + layer * (2 * 6 * MATSZ);
    const unsigned short* BtLo = BtHi + 6 * MATSZ;

    // ---- issue cp.async for B(r=0) first, then convert A while it flies ----
    {
        const char* shp = (const char*)(BtHi);
        const char* slp = (const char*)(BtLo);
#pragma unroll
        for (int i = 0; i < 17; i++) {
            int off = (tid + i * 256) * 16;
            if (off < MATSZ * 2) {
                cpa16(sbase + SB_HI + off, shp + off);
                cpa16(sbase + SB_LO + off, slp + off);
            }
        }
        cpa_commit();
    }

    // ---- convert A tile (256 rows x 128 cols) to hi/lo bf16 padded SMEM ----
    {
        uint32_t* ah = (uint32_t*)(dsm + SA_HI);
        uint32_t* al = (uint32_t*)(dsm + SA_LO);
        for (int i = tid; i < MROWS * 64; i += 256) {
            int n = i >> 6, kp = i & 63;
            int grow = row0 + n;
            uint32_t ph = 0u, pl = 0u;
            if (grow < Nn) {
                float2 x = *((const float2*)(A + (long long)grow * 128) + kp);
                __nv_bfloat16 h0 = __float2bfloat16(x.x);
                __nv_bfloat16 h1 = __float2bfloat16(x.y);
                __nv_bfloat16 l0 = __float2bfloat16(x.x - __bfloat162float(h0));
                __nv_bfloat16 l1 = __float2bfloat16(x.y - __bfloat162float(h1));
                ph = ((uint32_t)(*(unsigned short*)&h1) << 16) | (*(unsigned short*)&h0);
                pl = ((uint32_t)(*(unsigned short*)&l1) << 16) | (*(unsigned short*)&l0);
            }
            ah[n * (LPAD / 2) + kp] = ph;
            al[n * (LPAD / 2) + kp] = pl;
        }
    }
    cpa_wait0();
    __syncthreads();

    // warp tiling: 4(m) x 2(n) warps, each 64(m) x 64(n)
    int wm0 = (w >> 1) * 64;
    int wn0 = (w & 1) * 64;
    // A x4 lane address: rows = m (16), koff = hi/lo 8
    int a_row = (lane & 15);
    int a_koff = (lane >> 4) << 3;
    // B x4 lane address: rows = n (2 nj groups of 8), koff 8
    int b_row = (lane & 7) | ((lane >> 4) << 3);
    int b_koff = ((lane >> 3) & 1) << 3;

#pragma unroll 1
    for (int r = 0; r < 6; r++) {
        float acc[4][8][4];
#pragma unroll
        for (int mi = 0; mi < 4; mi++)
#pragma unroll
            for (int nj = 0; nj < 8; nj++)
#pragma unroll
                for (int q = 0; q < 4; q++) acc[mi][nj][q] = 0.f;

        uint32_t aHiBase = sbase + SA_HI, aLoBase = sbase + SA_LO;
        uint32_t bHiBase = sbase + SB_HI, bLoBase = sbase + SB_LO;

#pragma unroll
        for (int kk = 0; kk < 8; kk++) {
            int k0 = kk * 16;
            uint32_t aHi[4][4], aLo[4][4], bHi[8][2], bLo[8][2];
#pragma unroll
            for (int mi = 0; mi < 4; mi++) {
                uint32_t off = (uint32_t)(((wm0 + mi * 16 + a_row) * LPAD + k0 + a_koff) * 2);
                ldm_x4(aHi[mi][0], aHi[mi][1], aHi[mi][2], aHi[mi][3], aHiBase + off);
                ldm_x4(aLo[mi][0], aLo[mi][1], aLo[mi][2], aLo[mi][3], aLoBase + off);
            }
#pragma unroll
            for (int njp = 0; njp < 4; njp++) {
                uint32_t off = (uint32_t)(((wn0 + njp * 16 + b_row) * LPAD + k0 + b_koff) * 2);
                ldm_x4(bHi[2 * njp][0], bHi[2 * njp][1], bHi[2 * njp + 1][0], bHi[2 * njp + 1][1], bHiBase + off);
                ldm_x4(bLo[2 * njp][0], bLo[2 * njp][1], bLo[2 * njp + 1][0], bLo[2 * njp + 1][1], bLoBase + off);
            }
            // 96 MMAs: aHi*bHi + aHi*bLo + aLo*bHi
#pragma unroll
            for (int mi = 0; mi < 4; mi++)
#pragma unroll
                for (int nj = 0; nj < 8; nj++)
                    mma_bf16(acc[mi][nj], aHi[mi], bHi[nj]);
#pragma unroll
            for (int mi = 0; mi < 4; mi++)
#pragma unroll
                for (int nj = 0; nj < 8; nj++)
                    mma_bf16(acc[mi][nj], aHi[mi], bLo[nj]);
#pragma unroll
            for (int mi = 0; mi < 4; mi++)
#pragma unroll
                for (int nj = 0; nj < 8; nj++)
                    mma_bf16(acc[mi][nj], aLo[mi], bHi[nj]);
        }
        __syncthreads();   // all MMAs done reading B(r) -> buffer free

        // prefetch B(r+1) under the epilogue
        if (r < 5) {
            const char* shp = (const char*)(BtHi + (r + 1) * MATSZ);
            const char* slp = (const char*)(BtLo + (r + 1) * MATSZ);
#pragma unroll
            for (int i = 0; i < 17; i++) {
                int off = (tid + i * 256) * 16;
                if (off < MATSZ * 2) {
                    cpa16(sbase + SB_HI + off, shp + off);
                    cpa16(sbase + SB_LO + off, slp + off);
                }
            }
            cpa_commit();
        }

        // epilogue writes (overlap with cp.async)
        int qr = lane >> 2, qc = lane & 3;
        float* outbase = (r < 5) ? (g_hW + (long long)r * Nn * 128) : g_agg;
#pragma unroll
        for (int mi = 0; mi < 4; mi++) {
            int grow0 = row0 + wm0 + mi * 16 + qr;
#pragma unroll
            for (int half = 0; half < 2; half++) {
                int grow = grow0 + half * 8;
                if (grow < Nn) {
                    float* op = outbase + (long long)grow * 128;
#pragma unroll
                    for (int nj = 0; nj < 8; nj++) {
                        int col = wn0 + nj * 8 + qc * 2;
                        float2 v;
                        v.x = acc[mi][nj][half * 2 + 0];
                        v.y = acc[mi][nj][half * 2 + 1];
                        if (r == 5) { v.x += bias[col]; v.y += bias[col + 1]; }
                        *(float2*)(op + col) = v;
                    }
                }
            }
        }
        if (r < 5) cpa_wait0();
        __syncthreads();
    }
}

// ---------------- zero/init ----------------
__global__ void zinit_k(int both) {
    int t = threadIdx.x;
    if (t < 256) g_stats[t] = 0.f;
    if (both && t < 2) g_E[t] = 0.0;
}

// ---------------- batched small FFMA GEMMs for disc (M=512), tasks via blockIdx.y ----------------
// mode 0: y0={fcx: feats[ego]@Wfc+bfc}, y1={cX: feats[ego]@Wlin2}
// mode 1: y0={aM: sm@Wlin1}, y1={rP: pos[ridxP]@Wlin0}, y2={rN: pos[ridxN]@Wlin0}
__global__ void __launch_bounds__(256) gemm_disc_k(
    const float* __restrict__ features, const int* __restrict__ ego_ids,
    const float* __restrict__ Wfc, const float* __restrict__ bfc,
    const float* __restrict__ Wlin, int mode)
{
    const float* A; const int* rowidx = (const int*)0;
    const float* B; const float* bias = (const float*)0; float* C;
    int task = blockIdx.y;
    if (mode == 0) {
        if (task == 0) { A = features; rowidx = ego_ids; B = Wfc; bias = bfc; C = g_fcx; }
        else           { A = features; rowidx = ego_ids; B = Wlin + 256 * 128; C = g_cX; }
    } else {
        if (task == 0)      { A = g_sm;  B = Wlin + 128 * 128; C = g_aM; }
        else if (task == 1) { A = g_pos; rowidx = g_ridxP; B = Wlin; C = g_rP; }
        else                { A = g_pos; rowidx = g_ridxN; B = Wlin; C = g_rN; }
    }
    __shared__ float As[32][132];
    __shared__ float Bs[32][132];
    const int row0 = blockIdx.x * 128;
    const int tid = threadIdx.x;
    const int tx = tid & 15, ty = tid >> 4;
    float acc[8][8];
#pragma unroll
    for (int i = 0; i < 8; i++)
#pragma unroll
        for (int j = 0; j < 8; j++) acc[i][j] = 0.f;

    for (int kk = 0; kk < 128; kk += 32) {
#pragma unroll
        for (int i = 0; i < 4; i++) {
            int idx = tid + i * 256;
            int rw = idx >> 3;
            int c4 = idx & 7;
            int grow = row0 + rw;
            float4 v = make_float4(0.f, 0.f, 0.f, 0.f);
            if (grow < NEGO) {
                int ar = rowidx ? rowidx[grow] : grow;
                v = *(const float4*)(A + (long long)ar * 128 + kk + c4 * 4);
            }
            As[c4 * 4 + 0][rw] = v.x;
            As[c4 * 4 + 1][rw] = v.y;
            As[c4 * 4 + 2][rw] = v.z;
            As[c4 * 4 + 3][rw] = v.w;
        }
#pragma unroll
        for (int i = 0; i < 4; i++) {
            int idx = tid + i * 256;
            int rw = idx >> 5;
            int c4 = idx & 31;
            float4 v = *(const float4*)(B + (long long)(kk + rw) * 128 + c4 * 4);
            *(float4*)&Bs[rw][c4 * 4] = v;
        }
        __syncthreads();
#pragma unroll
        for (int k = 0; k < 32; k++) {
            float a[8], b[8];
#pragma unroll
            for (int i = 0; i < 8; i++) a[i] = As[k][ty * 8 + i];
#pragma unroll
            for (int j = 0; j < 8; j++) b[j] = Bs[k][tx * 8 + j];
#pragma unroll
            for (int i = 0; i < 8; i++)
#pragma unroll
                for (int j = 0; j < 8; j++) acc[i][j] += a[i] * b[j];
        }
        __syncthreads();
    }
#pragma unroll
    for (int i = 0; i < 8; i++) {
        int grow = row0 + ty * 8 + i;
        if (grow >= NEGO) continue;
#pragma unroll
        for (int j = 0; j < 8; j++) {
            int col = tx * 8 + j;
            float v = acc[i][j];
            if (bias) v += bias[col];
            C[(long long)grow * 128 + col] = v;
        }
    }
}

// ---------------- edge scatter: g_agg[dst] += g_hW[etype][src] ----------------
__global__ void __launch_bounds__(256) scatter_k(
    const int* __restrict__ src, const int* __restrict__ dst, const int* __restrict__ et)
{
    int gw = (int)((blockIdx.x * blockDim.x + threadIdx.x) >> 5);
    int lane = threadIdx.x & 31;
    if (gw >= Ee) return;
    int s = src[gw], d = dst[gw], r = et[gw];
    float4 v = *((const float4*)(g_hW + ((long long)r * Nn + s) * 128) + lane);
    float* q = g_agg + (long long)d * 128 + lane * 4;
    asm volatile("red.global.add.v4.f32 [%0], {%1,%2,%3,%4};"
                 :: "l"(q), "f"(v.x), "f"(v.y), "f"(v.z), "f"(v.w) : "memory");
}

// ---------------- BN stats over leaky_relu(g_agg): per-col sum & sumsq ----------------
__global__ void __launch_bounds__(256) bnstats_k()
{
    int col = threadIdx.x & 127;
    int half = threadIdx.x >> 7;
    float s = 0.f, s2 = 0.f;
    for (long long r = (long long)blockIdx.x * 2 + half; r < Nn; r += (long long)gridDim.x * 2) {
        float v = g_agg[r * 128 + col];
        v = v >= 0.f ? v : 0.01f * v;
        s += v; s2 += v * v;
    }
    __shared__ float sh[256], sh2[256];
    sh[threadIdx.x] = s; sh2[threadIdx.x] = s2;
    __syncthreads();
    if (half == 0) {
        atomicAdd(&g_stats[col], s + sh[col + 128]);
        atomicAdd(&g_stats[128 + col], s2 + sh2[col + 128]);
    }
}

// ---------------- BN apply + relu ----------------
__global__ void __launch_bounds__(256) bnapply_k(int layer)
{
    long long i = (long long)blockIdx.x * blockDim.x + threadIdx.x;
    if (i >= (long long)Nn * 32) return;
    float4* Y = (float4*)(layer == 0 ? g_h1 : g_pos);
    int c4 = (int)(i & 31);
    float4 x = ((const float4*)g_agg)[i];
    float o[4]; float in[4] = {x.x, x.y, x.z, x.w};
#pragma unroll
    for (int j = 0; j < 4; j++) {
        int col = c4 * 4 + j;
        float mean = g_stats[col] * (1.0f / Nn);
        float var = g_stats[128 + col] * (1.0f / Nn) - mean * mean;
        float v = in[j];
        v = v >= 0.f ? v : 0.01f * v;
        float y = (v - mean) * rsqrtf(var + 1e-5f);
        o[j] = y > 0.f ? y : 0.f;
    }
    Y[i] = make_float4(o[0], o[1], o[2], o[3]);
}

// ---------------- disc structure prep (+ scan levelization) ----------------
__global__ void __launch_bounds__(512) discprep_k(
    const int* __restrict__ es, const int* __restrict__ ed,
    const int* __restrict__ ego, const int* __restrict__ perm)
{
    __shared__ unsigned adj[NEGO][16];
    __shared__ int spm[NEGO];
    __shared__ int rep[NEGO];
    int t = threadIdx.x;
#pragma unroll
    for (int w = 0; w < 16; w++) adj[t][w] = 0u;
    __syncthreads();
    for (int e = t; e < EEGO; e += 512) {
        int s = es[e], d = ed[e];
        if (s < d) atomicOr(&adj[d][s >> 5], 1u << (s & 31));
    }
    __syncthreads();
    int p = -1;
    int wj = t >> 5, bj = t & 31;
    unsigned m = bj ? (adj[t][wj] & ((1u << bj) - 1u)) : 0u;
    if (m) p = wj * 32 + 31 - __clz(m);
    for (int w = wj - 1; w >= 0 && p < 0; w--) {
        unsigned mm = adj[t][w];
        if (mm) p = w * 32 + 31 - __clz(mm);
    }
    spm[t] = p;
    g_pmax[t] = p;
    __syncthreads();
    if (t == 0) {
        for (int i = 0; i < NEGO; i++) {
            int pi = spm[i];
            rep[i] = (pi < 0) ? i : rep[pi];
        }
        // levelization: level[i] = 0 if p<0 or p==1 (no sm dependency), else level[p]+1
        int lev[NEGO];
        int cnt[NEGO + 1];
        for (int i = 0; i <= NEGO; i++) cnt[i] = 0;
        int maxl = 0;
        for (int i = 0; i < NEGO; i++) {
            int pi = spm[i];
            int l = (pi < 0 || pi == 1) ? 0 : lev[pi] + 1;
            lev[i] = l;
            cnt[l]++;
            if (l > maxl) maxl = l;
        }
        int run = 0;
        for (int l = 0; l <= maxl; l++) { g_lvls[l] = run; int c0 = cnt[l]; cnt[l] = run; run += c0; }
        g_lvls[maxl + 1] = run;
        for (int i = 0; i < NEGO; i++) g_order[cnt[lev[i]]++] = i;
        g_nlev = maxl + 1;
    }
    __syncthreads();
    int rid = ego[rep[t]];
    g_ridxP[t] = rid;
    g_ridxN[t] = perm[rid];
}

// ---------------- levelized snap_m recurrence ----------------
#define SCAN2_SMEM (16384 * 4 + 512 * 4)
__global__ void __launch_bounds__(512) scan2_k(
    const float* __restrict__ Wfc, const float* __restrict__ bfc)
{
    extern __shared__ float ssc[];
    float* Wsh = ssc;           // [k*128 + col]
    float* spb = ssc + 16384;   // [g*128 + k]
    int t = threadIdx.x, g = t >> 7, c = t & 127;
    for (int i = t; i < 16384; i += 512) Wsh[i] = Wfc[i];
    __syncthreads();
    float bfcc = bfc[c];
    float fcx1 = g_fcx[128 + c];
    int nlev = g_nlev;
    for (int L = 0; L < nlev; L++) {
        int s0 = g_lvls[L], s1 = g_lvls[L + 1];
        for (int idx = s0 + g; idx < s1; idx += 4) {
            int i = g_order[idx];
            int p = g_pmax[i];
            float v;
            if (p < 0) {
                v = 0.f;
            } else if (p == 1) {
                v = g_fcx[i * 128 + c] + fcx1;
                v = v > 0.f ? v : 0.f;
            } else {
                spb[g * 128 + c] = g_sm[p * 128 + c];
                asm volatile("bar.sync %0, 128;" :: "r"(g + 1) : "memory");
                float acc = bfcc;
#pragma unroll 8
                for (int k = 0; k < 128; k++) acc += spb[g * 128 + k] * Wsh[k * 128 + c];
                v = g_fcx[i * 128 + c] + acc;
                v = v > 0.f ? v : 0.f;
                asm volatile("bar.sync %0, 128;" :: "r"(g + 1) : "memory");
            }
            g_sm[i * 128 + c] = v;
        }
        __syncthreads();
    }
}

// ---------------- per-edge logits + JSD accumulation ----------------
__device__ __forceinline__ double softplus_d(double z) {
    return (z > 0.0) ? z + log1p(exp(-z)) : log1p(exp(z));
}

__global__ void __launch_bounds__(256) edgelogit_k(
    const int* __restrict__ es, const int* __restrict__ ed,
    const float* __restrict__ blin, const float* __restrict__ Wus,
    const float* __restrict__ bus)
{
    int gw = (int)((blockIdx.x * blockDim.x + threadIdx.x) >> 5);
    int lane = threadIdx.x & 31;
    if (gw >= EEGO) return;
    int s = es[gw], d = ed[gw];
    float lp = 0.f, ln = 0.f;
#pragma unroll
    for (int j = 0; j < 4; j++) {
        int c = lane * 4 + j;
        float base = g_aM[s * 128 + c] + g_cX[d * 128 + c] + blin[c];
        float w = Wus[c];
        float hp = base + g_rP[s * 128 + c]; hp = hp > 0.f ? hp : 0.f;
        float hn = base + g_rN[s * 128 + c]; hn = hn > 0.f ? hn : 0.f;
        lp += hp * w; ln += hn * w;
    }
#pragma unroll
    for (int o = 16; o; o >>= 1) {
        lp += __shfl_xor_sync(0xffffffffu, lp, o);
        ln += __shfl_xor_sync(0xffffffffu, ln, o);
    }
    if (lane == 0) {
        float bu = bus[0];
        double zp = (double)(lp + bu);
        double zn = (double)(ln + bu);
        atomicAdd(&g_E[0], LOG2C - softplus_d(-zp));
        atomicAdd(&g_E[1], softplus_d(-zn) + zn - LOG2C);
    }
}

__global__ void final_k(float* __restrict__ outp) {
    outp[0] = (float)((g_E[1] - g_E[0]) * (1.0 / (double)EEGO));
}

// ---------------- host ----------------
extern "C" void kernel_launch(void* const* d_in, const int* in_sizes, int n_in,
                              void* d_out, int out_size) {
    const float* features = (const float*)d_in[0];
    const float* W1     = (const float*)d_in[1];
    const float* Wloop1 = (const float*)d_in[2];
    const float* b1     = (const float*)d_in[3];
    const float* W2     = (const float*)d_in[4];
    const float* Wloop2 = (const float*)d_in[5];
    const float* b2     = (const float*)d_in[6];
    const float* Wfc    = (const float*)d_in[7];
    const float* bfc    = (const float*)d_in[8];
    const float* Wlin   = (const float*)d_in[9];
    const float* blin   = (const float*)d_in[10];
    const float* Wus    = (const float*)d_in[11];
    const float* bus    = (const float*)d_in[12];
    const int* src      = (const int*)d_in[13];
    const int* dst      = (const int*)d_in[14];
    const int* etype    = (const int*)d_in[15];
    const int* perm     = (const int*)d_in[16];
    const int* ego_ids  = (const int*)d_in[17];
    const int* ego_src  = (const int*)d_in[18];
    const int* ego_dst  = (const int*)d_in[19];

    cudaFuncSetAttribute(rgemm_k, cudaFuncAttributeMaxDynamicSharedMemorySize, SMEM_DYN);
    cudaFuncSetAttribute(scan2_k, cudaFuncAttributeMaxDynamicSharedMemorySize, SCAN2_SMEM);

    const int mt = (Nn + MROWS - 1) / MROWS;   // 391 row tiles
    const int scat_blocks = (Ee * 32) / 256;   // 100000
    const int bna_blocks = (Nn * 32 + 255) / 256;

    zinit_k<<<1, 256>>>(1);
    wprep_k<<<dim3(6, 4), 256>>>(W1, Wloop1, 0);
    wprep_k<<<dim3(6, 4), 256>>>(W2, Wloop2, 1);

    // ---- encoder layer 1 ----
    rgemm_k<<<mt, 256, SMEM_DYN>>>(features, b1, 0);
    scatter_k<<<scat_blocks, 256>>>(src, dst, etype);
    bnstats_k<<<512, 256>>>();
    bnapply_k<<<bna_blocks, 256>>>(0);

    // ---- encoder layer 2 ----
    zinit_k<<<1, 256>>>(0);
    rgemm_k<<<mt, 256, SMEM_DYN>>>(features, b2, 1);
    scatter_k<<<scat_blocks, 256>>>(src, dst, etype);
    bnstats_k<<<512, 256>>>();
    bnapply_k<<<bna_blocks, 256>>>(1);

    // ---- discriminator ----
    discprep_k<<<1, 512>>>(ego_src, ego_dst, ego_ids, perm);
    gemm_disc_k<<<dim3(4, 2), 256>>>(features, ego_ids, Wfc, bfc, Wlin, 0);   // fcx, cX
    scan2_k<<<1, 512, SCAN2_SMEM>>>(Wfc, bfc);
    gemm_disc_k<<<dim3(4, 3), 256>>>(features, ego_ids, Wfc, bfc, Wlin, 1);   // aM, rP, rN
    edgelogit_k<<<512, 256>>>(ego_src, ego_dst, blin, Wus, bus);
    final_k<<<1, 1>>>((float*)d_out);
}

// round 10
// speedup vs baseline: 2.1980x; 1.0017x over previous
#include <cuda_runtime.h>
#include <cuda_bf16.h>
#include <stdint.h>
#include <math.h>

#define Nn 100000
#define Ee 800000
#define NEGO 512
#define EEGO 4096
#define RR 5
#define HH 128
#define LOG2C 0.6931471805599453

// ---------------- scratch (device globals; no allocation allowed) ----------------
__device__ float g_hW[(size_t)RR * Nn * HH];   // 256 MB
__device__ float g_agg[(size_t)Nn * HH];       // 51 MB
__device__ float g_pos[(size_t)Nn * HH];       // 51 MB
__device__ float g_stats[256];
__device__ float g_fcx[NEGO * HH];
__device__ float g_sm[NEGO * HH];
__device__ float g_aM[NEGO * HH];
__device__ float g_cX[NEGO * HH];
__device__ float g_rP[NEGO * HH];
__device__ float g_rN[NEGO * HH];
__device__ int   g_pmax[NEGO];
__device__ int   g_ridxP[NEGO];
__device__ int   g_ridxN[NEGO];
__device__ int   g_order[NEGO];
__device__ int   g_lvls[NEGO + 1];
__device__ int   g_nlev;
__device__ double g_E[2];
// transposed bf16 weight images [N=128][Kpad=136] per mat:
// layout: [layer(2)][half(2: hi,lo)][mat(6)][17408]
#define LPAD 136
#define MATSZ (128 * LPAD)   // 17408 halves
__device__ __align__(256) unsigned short g_Bt[2 * 2 * 6 * MATSZ];

// ---------------- PTX helpers (baseline sm_100-legal) ----------------
__device__ __forceinline__ uint32_t smem_u32(const void* p) {
    uint32_t a;
    asm("{ .reg .u64 t; cvta.to.shared.u64 t, %1; cvt.u32.u64 %0, t; }" : "=r"(a) : "l"(p));
    return a;
}
__device__ __forceinline__ void ldm_x4(uint32_t& r0, uint32_t& r1, uint32_t& r2, uint32_t& r3, uint32_t addr) {
    asm volatile("ldmatrix.sync.aligned.m8n8.x4.shared.b16 {%0,%1,%2,%3}, [%4];"
                 : "=r"(r0), "=r"(r1), "=r"(r2), "=r"(r3) : "r"(addr));
}
__device__ __forceinline__ void mma_bf16(float* d, const uint32_t* a, const uint32_t* b) {
    asm volatile("mma.sync.aligned.m16n8k16.row.col.f32.bf16.bf16.f32 "
                 "{%0,%1,%2,%3}, {%4,%5,%6,%7}, {%8,%9}, {%0,%1,%2,%3};"
                 : "+f"(d[0]), "+f"(d[1]), "+f"(d[2]), "+f"(d[3])
                 : "r"(a[0]), "r"(a[1]), "r"(a[2]), "r"(a[3]), "r"(b[0]), "r"(b[1]));
}
__device__ __forceinline__ void cpa16(uint32_t smaddr, const void* g) {
    asm volatile("cp.async.cg.shared.global [%0], [%1], 16;" :: "r"(smaddr), "l"(g) : "memory");
}
__device__ __forceinline__ void cpa_commit() { asm volatile("cp.async.commit_group;" ::: "memory"); }
__device__ __forceinline__ void cpa_wait0() { asm volatile("cp.async.wait_group 0;" ::: "memory"); }

// ---------------- weight prep: transpose + hi/lo split into padded [N][Kpad] ----------------
__global__ void wprep_k(const float* __restrict__ W, const float* __restrict__ Wloop, int layer)
{
    int r = blockIdx.x;
    unsigned short* oh = g_Bt + layer * (2 * 6 * MATSZ) + r * MATSZ;
    unsigned short* ol = oh + 6 * MATSZ;
    const float* src = (r < 5) ? (W + r * 16384) : Wloop;
    int base = blockIdx.y * 4096;
    for (int idx = base + threadIdx.x; idx < base + 4096; idx += blockDim.x) {
        int n = idx >> 7, k = idx & 127;
        float x = src[k * 128 + n];
        __nv_bfloat16 h = __float2bfloat16(x);
        __nv_bfloat16 l = __float2bfloat16(x - __bfloat162float(h));
        oh[n * LPAD + k] = *(unsigned short*)&h;
        ol[n * LPAD + k] = *(unsigned short*)&l;
    }
}

// ---------------- fused relation GEMM (mma.sync bf16-split, 12 warps, inline BN for layer2) ----
#define MROWS 192
#define SA_HI 0
#define SA_LO 52224
#define SB_HI 104448
#define SB_LO 139264
#define SMEM_DYN 174080

__global__ void __launch_bounds__(384, 1) rgemm_k(const float* __restrict__ Aext,
                                                  const float* __restrict__ bias, int layer)
{
    extern __shared__ char dsm[];
    __shared__ float s_mean[128], s_rstd[128];
    uint32_t sbase = smem_u32(dsm);
    int tid = threadIdx.x;
    int wid = tid >> 5, lane = tid & 31;
    int row0 = blockIdx.x * MROWS;
    const unsigned short* BtHi = g_Bt + layer * (2 * 6 * MATSZ);
    const unsigned short* BtLo = BtHi + 6 * MATSZ;

    // ---- issue cp.async for B(r=0) first ----
    {
        const char* shp = (const char*)(BtHi);
        const char* slp = (const char*)(BtLo);
#pragma unroll
        for (int i = 0; i < 6; i++) {
            int off = (tid + i * 384) * 16;
            if (off < MATSZ * 2) {
                cpa16(sbase + SB_HI + off, shp + off);
                cpa16(sbase + SB_LO + off, slp + off);
            }
        }
        cpa_commit();
    }

    // ---- layer-2: BN params into static smem ----
    if (layer == 1) {
        if (tid < 128) {
            float m = g_stats[tid] * (1.0f / Nn);
            float var = g_stats[128 + tid] * (1.0f / Nn) - m * m;
            s_mean[tid] = m;
            s_rstd[tid] = rsqrtf(var + 1e-5f);
        }
        __syncthreads();
    }

    // ---- convert A tile (192 rows x 128 cols) to hi/lo bf16 padded SMEM ----
    {
        const float* A = (layer == 0) ? Aext : g_agg;
        uint32_t* ah = (uint32_t*)(dsm + SA_HI);
        uint32_t* al = (uint32_t*)(dsm + SA_LO);
        for (int i = tid; i < MROWS * 64; i += 384) {
            int n = i >> 6, kp = i & 63;
            int grow = row0 + n;
            uint32_t ph = 0u, pl = 0u;
            if (grow < Nn) {
                float2 x = *((const float2*)(A + (long long)grow * 128) + kp);
                if (layer == 1) {
                    int c0 = kp * 2;
                    float v0 = x.x >= 0.f ? x.x : 0.01f * x.x;
                    float v1 = x.y >= 0.f ? x.y : 0.01f * x.y;
                    v0 = (v0 - s_mean[c0]) * s_rstd[c0];
                    v1 = (v1 - s_mean[c0 + 1]) * s_rstd[c0 + 1];
                    x.x = v0 > 0.f ? v0 : 0.f;
                    x.y = v1 > 0.f ? v1 : 0.f;
                }
                __nv_bfloat16 h0 = __float2bfloat16(x.x);
                __nv_bfloat16 h1 = __float2bfloat16(x.y);
                __nv_bfloat16 l0 = __float2bfloat16(x.x - __bfloat162float(h0));
                __nv_bfloat16 l1 = __float2bfloat16(x.y - __bfloat162float(h1));
                ph = ((uint32_t)(*(unsigned short*)&h1) << 16) | (*(unsigned short*)&h0);
                pl = ((uint32_t)(*(unsigned short*)&l1) << 16) | (*(unsigned short*)&l0);
            }
            ah[n * (LPAD / 2) + kp] = ph;
            al[n * (LPAD / 2) + kp] = pl;
        }
    }
    cpa_wait0();
    __syncthreads();

    // warp tiling: 3(m) x 4(n) warps, each 64(m) x 32(n)
    int wm0 = (wid % 3) * 64;
    int wn0 = (wid / 3) * 32;
    int a_row = (lane & 15);
    int a_koff = (lane >> 4) << 3;
    int b_row = (lane & 7) | ((lane >> 4) << 3);
    int b_koff = ((lane >> 3) & 1) << 3;

#pragma unroll 1
    for (int r = 0; r < 6; r++) {
        float acc[4][4][4];
#pragma unroll
        for (int mi = 0; mi < 4; mi++)
#pragma unroll
            for (int nj = 0; nj < 4; nj++)
#pragma unroll
                for (int q = 0; q < 4; q++) acc[mi][nj][q] = 0.f;

        uint32_t aHiBase = sbase + SA_HI, aLoBase = sbase + SA_LO;
        uint32_t bHiBase = sbase + SB_HI, bLoBase = sbase + SB_LO;

#pragma unroll
        for (int kk = 0; kk < 8; kk++) {
            int k0 = kk * 16;
            uint32_t aHi[4][4], aLo[4][4], bHi[4][2], bLo[4][2];
#pragma unroll
            for (int mi = 0; mi < 4; mi++) {
                uint32_t off = (uint32_t)(((wm0 + mi * 16 + a_row) * LPAD + k0 + a_koff) * 2);
                ldm_x4(aHi[mi][0], aHi[mi][1], aHi[mi][2], aHi[mi][3], aHiBase + off);
                ldm_x4(aLo[mi][0], aLo[mi][1], aLo[mi][2], aLo[mi][3], aLoBase + off);
            }
#pragma unroll
            for (int njp = 0; njp < 2; njp++) {
                uint32_t off = (uint32_t)(((wn0 + njp * 16 + b_row) * LPAD + k0 + b_koff) * 2);
                ldm_x4(bHi[2 * njp][0], bHi[2 * njp][1], bHi[2 * njp + 1][0], bHi[2 * njp + 1][1], bHiBase + off);
                ldm_x4(bLo[2 * njp][0], bLo[2 * njp][1], bLo[2 * njp + 1][0], bLo[2 * njp + 1][1], bLoBase + off);
            }
            // 48 MMAs: aHi*bHi + aHi*bLo + aLo*bHi
#pragma unroll
            for (int mi = 0; mi < 4; mi++)
#pragma unroll
                for (int nj = 0; nj < 4; nj++)
                    mma_bf16(acc[mi][nj], aHi[mi], bHi[nj]);
#pragma unroll
            for (int mi = 0; mi < 4; mi++)
#pragma unroll
                for (int nj = 0; nj < 4; nj++)
                    mma_bf16(acc[mi][nj], aHi[mi], bLo[nj]);
#pragma unroll
            for (int mi = 0; mi < 4; mi++)
#pragma unroll
                for (int nj = 0; nj < 4; nj++)
                    mma_bf16(acc[mi][nj], aLo[mi], bHi[nj]);
        }
        __syncthreads();   // all MMAs done reading B(r) -> buffer free

        // prefetch B(r+1) under the epilogue
        if (r < 5) {
            const char* shp = (const char*)(BtHi + (r + 1) * MATSZ);
            const char* slp = (const char*)(BtLo + (r + 1) * MATSZ);
#pragma unroll
            for (int i = 0; i < 6; i++) {
                int off = (tid + i * 384) * 16;
                if (off < MATSZ * 2) {
                    cpa16(sbase + SB_HI + off, shp + off);
                    cpa16(sbase + SB_LO + off, slp + off);
                }
            }
            cpa_commit();
        }

        // epilogue writes (overlap with cp.async)
        int qr = lane >> 2, qc = lane & 3;
        float* outbase = (r < 5) ? (g_hW + (long long)r * Nn * 128) : g_agg;
#pragma unroll
        for (int mi = 0; mi < 4; mi++) {
            int grow0 = row0 + wm0 + mi * 16 + qr;
#pragma unroll
            for (int half = 0; half < 2; half++) {
                int grow = grow0 + half * 8;
                if (grow < Nn) {
                    float* op = outbase + (long long)grow * 128;
#pragma unroll
                    for (int nj = 0; nj < 4; nj++) {
                        int col = wn0 + nj * 8 + qc * 2;
                        float2 v;
                        v.x = acc[mi][nj][half * 2 + 0];
                        v.y = acc[mi][nj][half * 2 + 1];
                        if (r == 5) { v.x += bias[col]; v.y += bias[col + 1]; }
                        *(float2*)(op + col) = v;
                    }
                }
            }
        }
        if (r < 5) cpa_wait0();
        __syncthreads();
    }
}

// ---------------- zero/init ----------------
__global__ void zinit_k(int both) {
    int t = threadIdx.x;
    if (t < 256) g_stats[t] = 0.f;
    if (both && t < 2) g_E[t] = 0.0;
}

// ---------------- batched small FFMA GEMMs for disc (M=512) ----------------
__global__ void __launch_bounds__(256) gemm_disc_k(
    const float* __restrict__ features, const int* __restrict__ ego_ids,
    const float* __restrict__ Wfc, const float* __restrict__ bfc,
    const float* __restrict__ Wlin, int mode)
{
    const float* A; const int* rowidx = (const int*)0;
    const float* B; const float* bias = (const float*)0; float* C;
    int task = blockIdx.y;
    if (mode == 0) {
        if (task == 0) { A = features; rowidx = ego_ids; B = Wfc; bias = bfc; C = g_fcx; }
        else           { A = features; rowidx = ego_ids; B = Wlin + 256 * 128; C = g_cX; }
    } else {
        if (task == 0)      { A = g_sm;  B = Wlin + 128 * 128; C = g_aM; }
        else if (task == 1) { A = g_pos; rowidx = g_ridxP; B = Wlin; C = g_rP; }
        else                { A = g_pos; rowidx = g_ridxN; B = Wlin; C = g_rN; }
    }
    __shared__ float As[32][132];
    __shared__ float Bs[32][132];
    const int row0 = blockIdx.x * 128;
    const int tid = threadIdx.x;
    const int tx = tid & 15, ty = tid >> 4;
    float acc[8][8];
#pragma unroll
    for (int i = 0; i < 8; i++)
#pragma unroll
        for (int j = 0; j < 8; j++) acc[i][j] = 0.f;

    for (int kk = 0; kk < 128; kk += 32) {
#pragma unroll
        for (int i = 0; i < 4; i++) {
            int idx = tid + i * 256;
            int rw = idx >> 3;
            int c4 = idx & 7;
            int grow = row0 + rw;
            float4 v = make_float4(0.f, 0.f, 0.f, 0.f);
            if (grow < NEGO) {
                int ar = rowidx ? rowidx[grow] : grow;
                v = *(const float4*)(A + (long long)ar * 128 + kk + c4 * 4);
            }
            As[c4 * 4 + 0][rw] = v.x;
            As[c4 * 4 + 1][rw] = v.y;
            As[c4 * 4 + 2][rw] = v.z;
            As[c4 * 4 + 3][rw] = v.w;
        }
#pragma unroll
        for (int i = 0; i < 4; i++) {
            int idx = tid + i * 256;
            int rw = idx >> 5;
            int c4 = idx & 31;
            float4 v = *(const float4*)(B + (long long)(kk + rw) * 128 + c4 * 4);
            *(float4*)&Bs[rw][c4 * 4] = v;
        }
        __syncthreads();
#pragma unroll
        for (int k = 0; k < 32; k++) {
            float a[8], b[8];
#pragma unroll
            for (int i = 0; i < 8; i++) a[i] = As[k][ty * 8 + i];
#pragma unroll
            for (int j = 0; j < 8; j++) b[j] = Bs[k][tx * 8 + j];
#pragma unroll
            for (int i = 0; i < 8; i++)
#pragma unroll
                for (int j = 0; j < 8; j++) acc[i][j] += a[i] * b[j];
        }
        __syncthreads();
    }
#pragma unroll
    for (int i = 0; i < 8; i++) {
        int grow = row0 + ty * 8 + i;
        if (grow >= NEGO) continue;
#pragma unroll
        for (int j = 0; j < 8; j++) {
            int col = tx * 8 + j;
            float v = acc[i][j];
            if (bias) v += bias[col];
            C[(long long)grow * 128 + col] = v;
        }
    }
}

// ---------------- edge scatter: g_agg[dst] += g_hW[etype][src] ----------------
__global__ void __launch_bounds__(256) scatter_k(
    const int* __restrict__ src, const int* __restrict__ dst, const int* __restrict__ et)
{
    int gw = (int)((blockIdx.x * blockDim.x + threadIdx.x) >> 5);
    int lane = threadIdx.x & 31;
    if (gw >= Ee) return;
    int s = src[gw], d = dst[gw], r = et[gw];
    float4 v = *((const float4*)(g_hW + ((long long)r * Nn + s) * 128) + lane);
    float* q = g_agg + (long long)d * 128 + lane * 4;
    asm volatile("red.global.add.v4.f32 [%0], {%1,%2,%3,%4};"
                 :: "l"(q), "f"(v.x), "f"(v.y), "f"(v.z), "f"(v.w) : "memory");
}

// ---------------- BN stats over leaky_relu(g_agg): per-col sum & sumsq ----------------
__global__ void __launch_bounds__(256) bnstats_k()
{
    int col = threadIdx.x & 127;
    int half = threadIdx.x >> 7;
    float s = 0.f, s2 = 0.f;
    for (long long r = (long long)blockIdx.x * 2 + half; r < Nn; r += (long long)gridDim.x * 2) {
        float v = g_agg[r * 128 + col];
        v = v >= 0.f ? v : 0.01f * v;
        s += v; s2 += v * v;
    }
    __shared__ float sh[256], sh2[256];
    sh[threadIdx.x] = s; sh2[threadIdx.x] = s2;
    __syncthreads();
    if (half == 0) {
        atomicAdd(&g_stats[col], s + sh[col + 128]);
        atomicAdd(&g_stats[128 + col], s2 + sh2[col + 128]);
    }
}

// ---------------- BN apply + relu (layer-2 output -> g_pos) ----------------
__global__ void __launch_bounds__(256) bnapply_k()
{
    long long i = (long long)blockIdx.x * blockDim.x + threadIdx.x;
    if (i >= (long long)Nn * 32) return;
    float4* Y = (float4*)g_pos;
    int c4 = (int)(i & 31);
    float4 x = ((const float4*)g_agg)[i];
    float o[4]; float in[4] = {x.x, x.y, x.z, x.w};
#pragma unroll
    for (int j = 0; j < 4; j++) {
        int col = c4 * 4 + j;
        float mean = g_stats[col] * (1.0f / Nn);
        float var = g_stats[128 + col] * (1.0f / Nn) - mean * mean;
        float v = in[j];
        v = v >= 0.f ? v : 0.01f * v;
        float y = (v - mean) * rsqrtf(var + 1e-5f);
        o[j] = y > 0.f ? y : 0.f;
    }
    Y[i] = make_float4(o[0], o[1], o[2], o[3]);
}

// ---------------- disc structure prep (+ scan levelization) ----------------
__global__ void __launch_bounds__(512) discprep_k(
    const int* __restrict__ es, const int* __restrict__ ed,
    const int* __restrict__ ego, const int* __restrict__ perm)
{
    __shared__ unsigned adj[NEGO][16];
    __shared__ int spm[NEGO];
    __shared__ int rep[NEGO];
    int t = threadIdx.x;
#pragma unroll
    for (int w = 0; w < 16; w++) adj[t][w] = 0u;
    __syncthreads();
    for (int e = t; e < EEGO; e += 512) {
        int s = es[e], d = ed[e];
        if (s < d) atomicOr(&adj[d][s >> 5], 1u << (s & 31));
    }
    __syncthreads();
    int p = -1;
    int wj = t >> 5, bj = t & 31;
    unsigned m = bj ? (adj[t][wj] & ((1u << bj) - 1u)) : 0u;
    if (m) p = wj * 32 + 31 - __clz(m);
    for (int w = wj - 1; w >= 0 && p < 0; w--) {
        unsigned mm = adj[t][w];
        if (mm) p = w * 32 + 31 - __clz(mm);
    }
    spm[t] = p;
    g_pmax[t] = p;
    __syncthreads();
    if (t == 0) {
        for (int i = 0; i < NEGO; i++) {
            int pi = spm[i];
            rep[i] = (pi < 0) ? i : rep[pi];
        }
        int lev[NEGO];
        int cnt[NEGO + 1];
        for (int i = 0; i <= NEGO; i++) cnt[i] = 0;
        int maxl = 0;
        for (int i = 0; i < NEGO; i++) {
            int pi = spm[i];
            int l = (pi < 0 || pi == 1) ? 0 : lev[pi] + 1;
            lev[i] = l;
            cnt[l]++;
            if (l > maxl) maxl = l;
        }
        int run = 0;
        for (int l = 0; l <= maxl; l++) { g_lvls[l] = run; int c0 = cnt[l]; cnt[l] = run; run += c0; }
        g_lvls[maxl + 1] = run;
        for (int i = 0; i < NEGO; i++) g_order[cnt[lev[i]]++] = i;
        g_nlev = maxl + 1;
    }
    __syncthreads();
    int rid = ego[rep[t]];
    g_ridxP[t] = rid;
    g_ridxN[t] = perm[rid];
}

// ---------------- levelized snap_m recurrence ----------------
#define SCAN2_SMEM (16384 * 4 + 512 * 4)
__global__ void __launch_bounds__(512) scan2_k(
    const float* __restrict__ Wfc, const float* __restrict__ bfc)
{
    extern __shared__ float ssc[];
    float* Wsh = ssc;           // [k*128 + col]
    float* spb = ssc + 16384;   // [g*128 + k]
    int t = threadIdx.x, g = t >> 7, c = t & 127;
    for (int i = t; i < 16384; i += 512) Wsh[i] = Wfc[i];
    __syncthreads();
    float bfcc = bfc[c];
    float fcx1 = g_fcx[128 + c];
    int nlev = g_nlev;
    for (int L = 0; L < nlev; L++) {
        int s0 = g_lvls[L], s1 = g_lvls[L + 1];
        for (int idx = s0 + g; idx < s1; idx += 4) {
            int i = g_order[idx];
            int p = g_pmax[i];
            float v;
            if (p < 0) {
                v = 0.f;
            } else if (p == 1) {
                v = g_fcx[i * 128 + c] + fcx1;
                v = v > 0.f ? v : 0.f;
            } else {
                spb[g * 128 + c] = g_sm[p * 128 + c];
                asm volatile("bar.sync %0, 128;" :: "r"(g + 1) : "memory");
                float acc = bfcc;
#pragma unroll 8
                for (int k = 0; k < 128; k++) acc += spb[g * 128 + k] * Wsh[k * 128 + c];
                v = g_fcx[i * 128 + c] + acc;
                v = v > 0.f ? v : 0.f;
                asm volatile("bar.sync %0, 128;" :: "r"(g + 1) : "memory");
            }
            g_sm[i * 128 + c] = v;
        }
        __syncthreads();
    }
}

// ---------------- per-edge logits + JSD accumulation ----------------
__device__ __forceinline__ double softplus_d(double z) {
    return (z > 0.0) ? z + log1p(exp(-z)) : log1p(exp(z));
}

__global__ void __launch_bounds__(256) edgelogit_k(
    const int* __restrict__ es, const int* __restrict__ ed,
    const float* __restrict__ blin, const float* __restrict__ Wus,
    const float* __restrict__ bus)
{
    int gw = (int)((blockIdx.x * blockDim.x + threadIdx.x) >> 5);
    int lane = threadIdx.x & 31;
    if (gw >= EEGO) return;
    int s = es[gw], d = ed[gw];
    float lp = 0.f, ln = 0.f;
#pragma unroll
    for (int j = 0; j < 4; j++) {
        int c = lane * 4 + j;
        float base = g_aM[s * 128 + c] + g_cX[d * 128 + c] + blin[c];
        float w = Wus[c];
        float hp = base + g_rP[s * 128 + c]; hp = hp > 0.f ? hp : 0.f;
        float hn = base + g_rN[s * 128 + c]; hn = hn > 0.f ? hn : 0.f;
        lp += hp * w; ln += hn * w;
    }
#pragma unroll
    for (int o = 16; o; o >>= 1) {
        lp += __shfl_xor_sync(0xffffffffu, lp, o);
        ln += __shfl_xor_sync(0xffffffffu, ln, o);
    }
    if (lane == 0) {
        float bu = bus[0];
        double zp = (double)(lp + bu);
        double zn = (double)(ln + bu);
        atomicAdd(&g_E[0], LOG2C - softplus_d(-zp));
        atomicAdd(&g_E[1], softplus_d(-zn) + zn - LOG2C);
    }
}

__global__ void final_k(float* __restrict__ outp) {
    outp[0] = (float)((g_E[1] - g_E[0]) * (1.0 / (double)EEGO));
}

// ---------------- host ----------------
extern "C" void kernel_launch(void* const* d_in, const int* in_sizes, int n_in,
                              void* d_out, int out_size) {
    const float* features = (const float*)d_in[0];
    const float* W1     = (const float*)d_in[1];
    const float* Wloop1 = (const float*)d_in[2];
    const float* b1     = (const float*)d_in[3];
    const float* W2     = (const float*)d_in[4];
    const float* Wloop2 = (const float*)d_in[5];
    const float* b2     = (const float*)d_in[6];
    const float* Wfc    = (const float*)d_in[7];
    const float* bfc    = (const float*)d_in[8];
    const float* Wlin   = (const float*)d_in[9];
    const float* blin   = (const float*)d_in[10];
    const float* Wus    = (const float*)d_in[11];
    const float* bus    = (const float*)d_in[12];
    const int* src      = (const int*)d_in[13];
    const int* dst      = (const int*)d_in[14];
    const int* etype    = (const int*)d_in[15];
    const int* perm     = (const int*)d_in[16];
    const int* ego_ids  = (const int*)d_in[17];
    const int* ego_src  = (const int*)d_in[18];
    const int* ego_dst  = (const int*)d_in[19];

    cudaFuncSetAttribute(rgemm_k, cudaFuncAttributeMaxDynamicSharedMemorySize, SMEM_DYN);
    cudaFuncSetAttribute(scan2_k, cudaFuncAttributeMaxDynamicSharedMemorySize, SCAN2_SMEM);

    const int mt = (Nn + MROWS - 1) / MROWS;   // 521 row tiles
    const int scat_blocks = (Ee * 32) / 256;   // 100000
    const int bna_blocks = (Nn * 32 + 255) / 256;

    zinit_k<<<1, 256>>>(1);
    wprep_k<<<dim3(6, 4), 256>>>(W1, Wloop1, 0);
    wprep_k<<<dim3(6, 4), 256>>>(W2, Wloop2, 1);

    // ---- encoder layer 1 ----
    rgemm_k<<<mt, 384, SMEM_DYN>>>(features, b1, 0);
    scatter_k<<<scat_blocks, 256>>>(src, dst, etype);
    bnstats_k<<<512, 256>>>();

    // ---- encoder layer 2 (BN of layer-1 applied inline in A-load) ----
    rgemm_k<<<mt, 384, SMEM_DYN>>>(features, b2, 1);
    zinit_k<<<1, 256>>>(0);
    scatter_k<<<scat_blocks, 256>>>(src, dst, etype);
    bnstats_k<<<512, 256>>>();
    bnapply_k<<<bna_blocks, 256>>>();

    // ---- discriminator ----
    discprep_k<<<1, 512>>>(ego_src, ego_dst, ego_ids, perm);
    gemm_disc_k<<<dim3(4, 2), 256>>>(features, ego_ids, Wfc, bfc, Wlin, 0);   // fcx, cX
    scan2_k<<<1, 512, SCAN2_SMEM>>>(Wfc, bfc);
    gemm_disc_k<<<dim3(4, 3), 256>>>(features, ego_ids, Wfc, bfc, Wlin, 1);   // aM, rP, rN
    edgelogit_k<<<512, 256>>>(ego_src, ego_dst, blin, Wus, bus);
    final_k<<<1, 1>>>((float*)d_out);
}